// round 9
// baseline (speedup 1.0000x reference)
#include <cuda_runtime.h>
#include <cuda_bf16.h>
#include <math.h>
#include <stdint.h>

#define S_LEN 512
#define BSZ   128
#define EDIM  300
#define HDIM  256
#define NCLS  6
#define PDIM  256

// LSTM cluster kernel geometry
#define CLU_SZ      8                 // CTAs per cluster
#define N_CLUSTERS  16                // 2 dirs x 8 batch-groups
#define LSTM_WS_BYTES (256 * 32 * 16) // 128 KB weight slice per CTA
#define LSTM_HS_ULL   (2 * 256 * 16)  // [buf][k][bl] dup'd h pairs
#define LSTM_SMEM   (LSTM_WS_BYTES + LSTM_HS_ULL * 8)   // 192 KB

// ---------------- scratch (device globals; no runtime allocation) ----------
__device__ float g_seq_emb[(size_t)S_LEN * BSZ * EDIM];              // 78.6 MB
__device__ float g_gx[2][(size_t)S_LEN * 4 * HDIM * BSZ];            // [dir][s][col][b] 536 MB
__device__ float g_h0[(size_t)BSZ * 2 * HDIM];                       // concat [fh, bh]
__device__ float g_gxc[NCLS * 3 * 2 * HDIM];                         // decoder input gates
__device__ float g_Wt4[2][HDIM][HDIM][4];                            // [dir][k][u][gate i,f,g,o]
__device__ float g_dWt4[2 * HDIM][2 * HDIM][4];                      // [k][u][gate r,z,n,pad]

// ---------------- helpers ---------------------------------------------------
__device__ __forceinline__ float sigmoidf_(float x) { return 1.0f / (1.0f + expf(-x)); }
__device__ __forceinline__ float tanhf_(float x) { return 1.0f - 2.0f / (expf(2.0f * x) + 1.0f); }

__device__ __forceinline__ unsigned long long pk2(float lo, float hi) {
    return ((unsigned long long)__float_as_uint(hi) << 32) | (unsigned long long)__float_as_uint(lo);
}
__device__ __forceinline__ float2 upk2(unsigned long long u) {
    float2 f; f.x = __uint_as_float((unsigned)u); f.y = __uint_as_float((unsigned)(u >> 32)); return f;
}
__device__ __forceinline__ void fma2(unsigned long long& d, unsigned long long a, unsigned long long b) {
    asm("fma.rn.f32x2 %0, %1, %2, %0;" : "+l"(d) : "l"(a), "l"(b));
}
__device__ __forceinline__ uint32_t smem_u32(const void* p) {
    uint32_t a;
    asm("{ .reg .u64 t; cvta.to.shared.u64 t, %1; cvt.u32.u64 %0, t; }" : "=r"(a) : "l"(p));
    return a;
}

// ---------------- kernel 0a: transpose LSTM Whh ------------------------------
__global__ __launch_bounds__(1024) void transpose_lstm_w(const float* __restrict__ fWhh,
                                                         const float* __restrict__ bWhh)
{
    __shared__ float t[32][33];
    const int dir = blockIdx.z >> 2;
    const int g   = blockIdx.z & 3;
    const int k0  = blockIdx.x * 32;
    const int u0  = blockIdx.y * 32;
    const int tx = threadIdx.x & 31, ty = threadIdx.x >> 5;
    const float* W = dir ? bWhh : fWhh;
    t[ty][tx] = W[(size_t)(g * HDIM + u0 + ty) * HDIM + k0 + tx];
    __syncthreads();
    g_Wt4[dir][k0 + ty][u0 + tx][g] = t[tx][ty];
}

// ---------------- kernel 0b: transpose decoder Whh ---------------------------
__global__ __launch_bounds__(1024) void transpose_dec_w(const float* __restrict__ dWhh)
{
    __shared__ float t[32][33];
    const int g  = blockIdx.z;
    const int k0 = blockIdx.x * 32;
    const int u0 = blockIdx.y * 32;
    const int tx = threadIdx.x & 31, ty = threadIdx.x >> 5;
    t[ty][tx] = dWhh[(size_t)(g * 2 * HDIM + u0 + ty) * (2 * HDIM) + k0 + tx];
    __syncthreads();
    g_dWt4[k0 + ty][u0 + tx][g] = t[tx][ty];
}

// ---------------- kernel 1: embedding gather + tanh, time-major -------------
__global__ void embed_kernel(const int* __restrict__ seq, const float* __restrict__ embW) {
    long long idx = (long long)blockIdx.x * blockDim.x + threadIdx.x;
    const long long total = (long long)S_LEN * BSZ * EDIM;
    if (idx >= total) return;
    int e = (int)(idx % EDIM);
    int r = (int)(idx / EDIM);
    int b = r % BSZ;
    int s = r / BSZ;
    int v = seq[b * S_LEN + s];
    g_seq_emb[idx] = tanhf_(embW[(long long)v * EDIM + e]);
}

// ---------------- kernel 2: input GEMMs, double-buffered smem ---------------
__global__ __launch_bounds__(256) void gx_gemm_kernel(
    const float* __restrict__ fWih, const float* __restrict__ fbih, const float* __restrict__ fbhh,
    const float* __restrict__ bWih, const float* __restrict__ bbih, const float* __restrict__ bbhh)
{
    __shared__ float As[2][16][128];
    __shared__ float Bs[2][16][128];

    const int dir   = blockIdx.z;
    const int s     = blockIdx.x;
    const int ntile = blockIdx.y;
    const float* W  = dir ? bWih : fWih;
    const float* bi = dir ? bbih : fbih;
    const float* bh = dir ? bbhh : fbhh;
    const int src_s = dir ? ((S_LEN - s) & (S_LEN - 1)) : s;
    const float* Abase = g_seq_emb + (size_t)src_s * BSZ * EDIM;

    const int t   = threadIdx.x;
    const int lr  = t & 127;
    const int lqp = t >> 7;
    const int tm  = t >> 4;
    const int tn  = t & 15;

    unsigned long long acc2[8][4];
#pragma unroll
    for (int i = 0; i < 8; i++)
#pragma unroll
        for (int j = 0; j < 4; j++) acc2[i][j] = 0ULL;

    const int NK = (EDIM + 15) / 16;   // 19
    float4 av[2], bv[2];
#pragma unroll
    for (int q = 0; q < 2; q++) {
        const int kk = (lqp * 2 + q) * 4;
        av[q] = make_float4(0.f, 0.f, 0.f, 0.f);
        bv[q] = make_float4(0.f, 0.f, 0.f, 0.f);
        if (kk + 3 < EDIM) {
            av[q] = *(const float4*)(W + (size_t)(ntile * 128 + lr) * EDIM + kk);
            bv[q] = *(const float4*)(Abase + (size_t)lr * EDIM + kk);
        }
    }
#pragma unroll
    for (int q = 0; q < 2; q++) {
        const int kb = (lqp * 2 + q) * 4;
        As[0][kb + 0][lr] = av[q].x; As[0][kb + 1][lr] = av[q].y;
        As[0][kb + 2][lr] = av[q].z; As[0][kb + 3][lr] = av[q].w;
        Bs[0][kb + 0][lr] = bv[q].x; Bs[0][kb + 1][lr] = bv[q].y;
        Bs[0][kb + 2][lr] = bv[q].z; Bs[0][kb + 3][lr] = bv[q].w;
    }

    for (int kt = 0; kt < NK; kt++) {
        __syncthreads();
        const int cur = kt & 1;
        const bool more = (kt + 1 < NK);
        if (more) {
#pragma unroll
            for (int q = 0; q < 2; q++) {
                const int kk = (kt + 1) * 16 + (lqp * 2 + q) * 4;
                av[q] = make_float4(0.f, 0.f, 0.f, 0.f);
                bv[q] = make_float4(0.f, 0.f, 0.f, 0.f);
                if (kk + 3 < EDIM) {
                    av[q] = *(const float4*)(W + (size_t)(ntile * 128 + lr) * EDIM + kk);
                    bv[q] = *(const float4*)(Abase + (size_t)lr * EDIM + kk);
                }
            }
        }
#pragma unroll
        for (int k = 0; k < 16; k++) {
            float4 aA = *(const float4*)&As[cur][k][tm * 8];
            float4 aB = *(const float4*)&As[cur][k][tm * 8 + 4];
            ulonglong2 bA = *(const ulonglong2*)&Bs[cur][k][4 * tn];
            ulonglong2 bB = *(const ulonglong2*)&Bs[cur][k][64 + 4 * tn];
            unsigned long long a[8];
            a[0] = pk2(aA.x, aA.x); a[1] = pk2(aA.y, aA.y);
            a[2] = pk2(aA.z, aA.z); a[3] = pk2(aA.w, aA.w);
            a[4] = pk2(aB.x, aB.x); a[5] = pk2(aB.y, aB.y);
            a[6] = pk2(aB.z, aB.z); a[7] = pk2(aB.w, aB.w);
#pragma unroll
            for (int i = 0; i < 8; i++) {
                fma2(acc2[i][0], a[i], bA.x);
                fma2(acc2[i][1], a[i], bA.y);
                fma2(acc2[i][2], a[i], bB.x);
                fma2(acc2[i][3], a[i], bB.y);
            }
        }
        if (more) {
            const int nxt = cur ^ 1;
#pragma unroll
            for (int q = 0; q < 2; q++) {
                const int kb = (lqp * 2 + q) * 4;
                As[nxt][kb + 0][lr] = av[q].x; As[nxt][kb + 1][lr] = av[q].y;
                As[nxt][kb + 2][lr] = av[q].z; As[nxt][kb + 3][lr] = av[q].w;
                Bs[nxt][kb + 0][lr] = bv[q].x; Bs[nxt][kb + 1][lr] = bv[q].y;
                Bs[nxt][kb + 2][lr] = bv[q].z; Bs[nxt][kb + 3][lr] = bv[q].w;
            }
        }
    }
    float* gbase = g_gx[dir] + (size_t)s * 1024 * 128;
#pragma unroll
    for (int i = 0; i < 8; i++) {
        const int col = ntile * 128 + tm * 8 + i;
        const float bb = bi[col] + bh[col];
        float2 v0 = upk2(acc2[i][0]), v1 = upk2(acc2[i][1]);
        float2 v2 = upk2(acc2[i][2]), v3 = upk2(acc2[i][3]);
        float4 oA = make_float4(v0.x + bb, v0.y + bb, v1.x + bb, v1.y + bb);
        float4 oB = make_float4(v2.x + bb, v2.y + bb, v3.x + bb, v3.y + bb);
        *(float4*)(gbase + (size_t)col * 128 + 4 * tn)      = oA;
        *(float4*)(gbase + (size_t)col * 128 + 64 + 4 * tn) = oB;
    }
}

// ---------------- kernel 3: cluster LSTM (DSMEM h exchange, no global sync) -
// 16 clusters x 8 CTAs x 256 threads. Cluster = (dir, 16-batch group).
// CTA rank r: units [32r, 32r+32), 128KB weight slice in smem.
// Thread: warp w -> units 4w..4w+3; lane l: ul=l>>3 (unit), bp=l&7 (2 batches).
// Per k: LDS.128 w (wi,wf)|(wg,wo) + LDS.128 dup'd h (b0,b0,b1,b1) + 4 FFMA2.
// h_next pushed dup'd to all 8 CTAs via st.shared::cluster; one
// barrier.cluster.arrive/wait per step (gx prefetch hidden in between).
__global__ __launch_bounds__(256) __cluster_dims__(CLU_SZ, 1, 1)
void lstm_cluster()
{
    extern __shared__ char smraw[];
    ulonglong2 (*ws)[32] = (ulonglong2(*)[32])smraw;                       // [k][ucta] 128KB
    unsigned long long* hsb = (unsigned long long*)(smraw + LSTM_WS_BYTES); // [buf][k][bl] 64KB

    const int blk = blockIdx.x;
    const int cid = blk >> 3;
    const int dir = cid >> 3;
    const int bg  = cid & 7;
    uint32_t rank;
    asm("mov.u32 %0, %%cluster_ctarank;" : "=r"(rank));
    const int t  = threadIdx.x;
    const int w  = t >> 5;
    const int l  = t & 31;
    const int ul = l >> 3;
    const int bp = l & 7;
    const int ucta  = 4 * w + ul;                 // 0..31
    const int uglob = 32 * (int)rank + ucta;      // 0..255
    const int bl0   = 2 * bp;                     // local batch 0..15
    const int bglob = 16 * bg + bl0;              // global batch

    // load this CTA's weight slice: ws[k][u] = (wi,wf | wg,wo) for unit 32r+u
    for (int i = 0; i < 32; i++) {
        int idx = i * 256 + t;
        int k = idx >> 5, uu = idx & 31;
        ws[k][uu] = *(const ulonglong2*)&g_Wt4[dir][k][32 * (int)rank + uu][0];
    }
    // zero h buffer 0 (own full copy)
    for (int i = t; i < 256 * 16; i += 256) hsb[i] = 0ULL;

    // peer base addresses of hs in every cluster CTA
    uint32_t my_hs = smem_u32(smraw) + LSTM_WS_BYTES;
    uint32_t peer[CLU_SZ];
#pragma unroll
    for (int r = 0; r < CLU_SZ; r++)
        asm("mapa.shared::cluster.u32 %0, %1, %2;" : "=r"(peer[r]) : "r"(my_hs), "r"(r));

    float c0 = 0.f, c1 = 0.f, h0v = 0.f, h1v = 0.f;

    const float* gxd = g_gx[dir];
    float2 gxq[4];
#pragma unroll
    for (int g = 0; g < 4; g++)
        gxq[g] = __ldcg((const float2*)(gxd + ((size_t)0 * 1024 + g * 256 + uglob) * 128 + bglob));

    // all smem copies initialized before first reads/pushes
    asm volatile("barrier.cluster.arrive.aligned;" ::: "memory");
    asm volatile("barrier.cluster.wait.aligned;" ::: "memory");

    for (int s = 0; s < S_LEN; s++) {
        const int buf = s & 1;
        const unsigned long long* hk = hsb + buf * 4096 + bl0;   // + k*16

        unsigned long long accif0 = 0ULL, accgo0 = 0ULL, accif1 = 0ULL, accgo1 = 0ULL;
#pragma unroll 8
        for (int k = 0; k < 256; k++) {
            ulonglong2 wv = ws[k][ucta];                          // (wi,wf)|(wg,wo)
            ulonglong2 hp = *(const ulonglong2*)(hk + k * 16);    // (h0,h0)|(h1,h1)
            fma2(accif0, wv.x, hp.x);
            fma2(accgo0, wv.y, hp.x);
            fma2(accif1, wv.x, hp.y);
            fma2(accgo1, wv.y, hp.y);
        }
        // cell update (2 batches)
        {
            float2 vif = upk2(accif0), vgo = upk2(accgo0);
            float gi = gxq[0].x + vif.x, gf = gxq[1].x + vif.y;
            float gg = gxq[2].x + vgo.x, go = gxq[3].x + vgo.y;
            float cc = sigmoidf_(gf) * c0 + sigmoidf_(gi) * tanhf_(gg);
            c0 = cc; h0v = sigmoidf_(go) * tanhf_(cc);
        }
        {
            float2 vif = upk2(accif1), vgo = upk2(accgo1);
            float gi = gxq[0].y + vif.x, gf = gxq[1].y + vif.y;
            float gg = gxq[2].y + vgo.x, go = gxq[3].y + vgo.y;
            float cc = sigmoidf_(gf) * c1 + sigmoidf_(gi) * tanhf_(gg);
            c1 = cc; h1v = sigmoidf_(go) * tanhf_(cc);
        }
        // push dup'd h pair to all 8 CTAs' hs[buf^1][uglob][bl0..bl0+1]
        {
            const uint32_t dst = (uint32_t)(((buf ^ 1) * 4096 + uglob * 16 + bl0) * 8);
            const unsigned long long d0 = pk2(h0v, h0v);
            const unsigned long long d1 = pk2(h1v, h1v);
#pragma unroll
            for (int r = 0; r < CLU_SZ; r++)
                asm volatile("st.shared::cluster.v2.u64 [%0], {%1, %2};"
                             :: "r"(peer[r] + dst), "l"(d0), "l"(d1) : "memory");
        }
        asm volatile("barrier.cluster.arrive.aligned;" ::: "memory");
        if (s + 1 < S_LEN) {
#pragma unroll
            for (int g = 0; g < 4; g++)
                gxq[g] = __ldcg((const float2*)(gxd + ((size_t)(s + 1) * 1024 + g * 256 + uglob) * 128 + bglob));
        }
        asm volatile("barrier.cluster.wait.aligned;" ::: "memory");
    }
    // final h -> g_h0[b][dir*256 + u]
    g_h0[(size_t)bglob * (2 * HDIM) + dir * HDIM + uglob]       = h0v;
    g_h0[(size_t)(bglob + 1) * (2 * HDIM) + dir * HDIM + uglob] = h1v;
}

// ---------------- kernel 4: decoder input gates ------------------------------
__global__ __launch_bounds__(256) void dec_prep_kernel(
    const int* __restrict__ classes, const float* __restrict__ ecW,
    const float* __restrict__ dWih, const float* __restrict__ dbih)
{
    __shared__ float ce[EDIM];
    const int c = blockIdx.x;
    const int cls = classes[c];
    for (int e = threadIdx.x; e < EDIM; e += blockDim.x)
        ce[e] = tanhf_(ecW[(size_t)cls * EDIM + e]);
    __syncthreads();
    const int j = blockIdx.y * 256 + threadIdx.x;
    float acc = dbih[j];
    const float4* w = (const float4*)(dWih + (size_t)j * EDIM);
#pragma unroll 5
    for (int k = 0; k < EDIM / 4; k++) {
        float4 wv = w[k];
        acc += wv.x * ce[4 * k] + wv.y * ce[4 * k + 1] + wv.z * ce[4 * k + 2] + wv.w * ce[4 * k + 3];
    }
    g_gxc[c * 1536 + j] = acc;
}

// ---------------- kernel 5: decoder GRU + proj + cls + log_softmax ----------
__global__ __launch_bounds__(512) void dec_kernel(
    const float* __restrict__ dbhh,
    const float* __restrict__ projW, const float* __restrict__ projB,
    const float* __restrict__ clsW, const float* __restrict__ clsB,
    float* __restrict__ out)
{
    const int Gd = 2;
    const int H2 = 2 * HDIM;
    const int b0 = blockIdx.x * Gd;
    const int u  = threadIdx.x;
    const ulonglong2* W2 = (const ulonglong2*)&g_dWt4[0][0][0];

    __shared__ unsigned long long hd[2][Gd][512];
    __shared__ float hplain[Gd][512];
    __shared__ float projs[Gd][PDIM];
    __shared__ float lgs[Gd][2];

    float hprev[Gd];
#pragma unroll
    for (int b = 0; b < Gd; b++) {
        hprev[b] = g_h0[(size_t)(b0 + b) * H2 + u];
        hd[0][b][u] = pk2(hprev[b], hprev[b]);
    }
    const float bhr = dbhh[u], bhz = dbhh[H2 + u], bhn = dbhh[2 * H2 + u];
    __syncthreads();

    for (int c = 0; c < NCLS; c++) {
        const int cur = c & 1, nxt = cur ^ 1;
        unsigned long long arz[Gd], anp[Gd];
#pragma unroll
        for (int b = 0; b < Gd; b++) { arz[b] = 0ULL; anp[b] = 0ULL; }
        const unsigned long long* h0p = &hd[cur][0][0];
        const unsigned long long* h1p = &hd[cur][1][0];

#pragma unroll 4
        for (int k = 0; k < H2; k++) {
            ulonglong2 wv = W2[k * H2 + u];
            unsigned long long hh0 = h0p[k], hh1 = h1p[k];
            fma2(arz[0], wv.x, hh0); fma2(anp[0], wv.y, hh0);
            fma2(arz[1], wv.x, hh1); fma2(anp[1], wv.y, hh1);
        }
        const float gxr = g_gxc[c * 1536 + u];
        const float gxz = g_gxc[c * 1536 + H2 + u];
        const float gxn = g_gxc[c * 1536 + 2 * H2 + u];
#pragma unroll
        for (int b = 0; b < Gd; b++) {
            float2 vrz = upk2(arz[b]);
            float2 vnp = upk2(anp[b]);
            float r = sigmoidf_(gxr + vrz.x + bhr);
            float z = sigmoidf_(gxz + vrz.y + bhz);
            float n = tanhf_(gxn + r * (vnp.x + bhn));
            float hn = tanhf_((1.0f - z) * n + z * hprev[b]);
            hprev[b] = hn;
            hd[nxt][b][u] = pk2(hn, hn);
            hplain[b][u] = hn;
        }
        __syncthreads();
        {
            const int b = u >> 8, p = u & 255;
            const float4* wv = (const float4*)(projW + (size_t)p * H2);
            const float4* hv = (const float4*)hplain[b];
            float acc = projB[p];
            for (int k4 = 0; k4 < H2 / 4; k4++) {
                float4 w4 = wv[k4], h4 = hv[k4];
                acc += w4.x * h4.x + w4.y * h4.y + w4.z * h4.z + w4.w * h4.w;
            }
            projs[b][p] = acc;
        }
        __syncthreads();
        const int wid = u >> 5, lid = u & 31;
        if (wid < Gd * 2) {
            const int b = wid >> 1, cl = wid & 1;
            float acc = 0.0f;
            for (int k = lid; k < PDIM; k += 32) acc += clsW[cl * PDIM + k] * projs[b][k];
#pragma unroll
            for (int o = 16; o > 0; o >>= 1) acc += __shfl_down_sync(0xffffffffu, acc, o);
            if (lid == 0) lgs[b][cl] = acc + clsB[cl];
        }
        __syncthreads();
        if (u < Gd) {
            const int b = u;
            float l0 = lgs[b][0], l1 = lgs[b][1];
            float m = fmaxf(l0, l1);
            float lse = m + logf(expf(l0 - m) + expf(l1 - m));
            out[(size_t)c * BSZ * 2 + (b0 + b) * 2 + 0] = l0 - lse;
            out[(size_t)c * BSZ * 2 + (b0 + b) * 2 + 1] = l1 - lse;
        }
        __syncthreads();
    }
}

// ---------------- launch -----------------------------------------------------
extern "C" void kernel_launch(void* const* d_in, const int* in_sizes, int n_in,
                              void* d_out, int out_size)
{
    const int*   seq     = (const int*)d_in[0];
    const int*   classes = (const int*)d_in[1];
    const float* embW    = (const float*)d_in[2];
    const float* ecW     = (const float*)d_in[3];
    const float* fWih    = (const float*)d_in[4];
    const float* fWhh    = (const float*)d_in[5];
    const float* fbih    = (const float*)d_in[6];
    const float* fbhh    = (const float*)d_in[7];
    const float* bWih    = (const float*)d_in[8];
    const float* bWhh    = (const float*)d_in[9];
    const float* bbih    = (const float*)d_in[10];
    const float* bbhh    = (const float*)d_in[11];
    const float* dWih    = (const float*)d_in[12];
    const float* dWhh    = (const float*)d_in[13];
    const float* dbih    = (const float*)d_in[14];
    const float* dbhh    = (const float*)d_in[15];
    const float* projW   = (const float*)d_in[16];
    const float* projB   = (const float*)d_in[17];
    const float* clsW    = (const float*)d_in[18];
    const float* clsB    = (const float*)d_in[19];
    float* out = (float*)d_out;

    cudaFuncSetAttribute(lstm_cluster, cudaFuncAttributeMaxDynamicSharedMemorySize, LSTM_SMEM);

    {   // 0. weight transposes
        dim3 gl(HDIM / 32, HDIM / 32, 8);
        transpose_lstm_w<<<gl, 1024>>>(fWhh, bWhh);
        dim3 gd(2 * HDIM / 32, 2 * HDIM / 32, 3);
        transpose_dec_w<<<gd, 1024>>>(dWhh);
    }
    {   // 1. embeddings
        long long total = (long long)S_LEN * BSZ * EDIM;
        int blocks = (int)((total + 255) / 256);
        embed_kernel<<<blocks, 256>>>(seq, embW);
    }
    {   // 2. input-gate GEMMs, double-buffered
        dim3 grid(S_LEN, 1024 / 128, 2);
        gx_gemm_kernel<<<grid, 256>>>(fWih, fbih, fbhh, bWih, bbih, bbhh);
    }
    {   // 3. cluster LSTM (DSMEM h exchange, no global barrier)
        lstm_cluster<<<N_CLUSTERS * CLU_SZ, 256, LSTM_SMEM>>>();
    }
    {   // 4. decoder input gates per class
        dim3 grid(NCLS, 6);
        dec_prep_kernel<<<grid, 256>>>(classes, ecW, dWih, dbih);
    }
    {   // 5. decoder GRU + projection + classifier + log_softmax
        dec_kernel<<<BSZ / 2, 512>>>(dbhh, projW, projB, clsW, clsB, out);
    }
    (void)in_sizes; (void)n_in; (void)out_size;
}

// round 10
// speedup vs baseline: 1.2640x; 1.2640x over previous
#include <cuda_runtime.h>
#include <cuda_bf16.h>
#include <math.h>

#define S_LEN 512
#define BSZ   128
#define EDIM  300
#define HDIM  256
#define NCLS  6
#define PDIM  256

// ---------------- scratch (device globals; no runtime allocation) ----------
__device__ float g_seq_emb[(size_t)S_LEN * BSZ * EDIM];              // 78.6 MB
__device__ float g_gx[2][(size_t)S_LEN * 4 * HDIM * BSZ];            // [dir][s][col][b] 536 MB
__device__ float g_h[2][2][HDIM][BSZ];                               // [dir][buf][u][b]
__device__ float g_c[2][HDIM][BSZ];                                  // cell state
__device__ float g_h0[(size_t)BSZ * 2 * HDIM];                       // concat [fh, bh]
__device__ float g_gxc[NCLS * 3 * 2 * HDIM];                         // decoder input gates
__device__ float g_Wt4[2][HDIM][HDIM][4];                            // [dir][k][u][gate i,f,g,o]
__device__ float g_dWt4[2 * HDIM][2 * HDIM][4];                      // [k][u][gate r,z,n,pad]

// ---------------- helpers ---------------------------------------------------
__device__ __forceinline__ float sigmoidf_(float x) { return 1.0f / (1.0f + expf(-x)); }
__device__ __forceinline__ float tanhf_(float x) { return 1.0f - 2.0f / (expf(2.0f * x) + 1.0f); }

__device__ __forceinline__ unsigned long long pk2(float lo, float hi) {
    return ((unsigned long long)__float_as_uint(hi) << 32) | (unsigned long long)__float_as_uint(lo);
}
__device__ __forceinline__ float2 upk2(unsigned long long u) {
    float2 f; f.x = __uint_as_float((unsigned)u); f.y = __uint_as_float((unsigned)(u >> 32)); return f;
}
__device__ __forceinline__ void fma2(unsigned long long& d, unsigned long long a, unsigned long long b) {
    asm("fma.rn.f32x2 %0, %1, %2, %0;" : "+l"(d) : "l"(a), "l"(b));
}
__device__ __forceinline__ void add2(unsigned long long& d, unsigned long long a) {
    asm("add.rn.f32x2 %0, %0, %1;" : "+l"(d) : "l"(a));
}

// ---------------- kernel 0a: transpose LSTM Whh ------------------------------
__global__ __launch_bounds__(1024) void transpose_lstm_w(const float* __restrict__ fWhh,
                                                         const float* __restrict__ bWhh)
{
    __shared__ float t[32][33];
    const int dir = blockIdx.z >> 2;
    const int g   = blockIdx.z & 3;
    const int k0  = blockIdx.x * 32;
    const int u0  = blockIdx.y * 32;
    const int tx = threadIdx.x & 31, ty = threadIdx.x >> 5;
    const float* W = dir ? bWhh : fWhh;
    t[ty][tx] = W[(size_t)(g * HDIM + u0 + ty) * HDIM + k0 + tx];
    __syncthreads();
    g_Wt4[dir][k0 + ty][u0 + tx][g] = t[tx][ty];
}

// ---------------- kernel 0b: transpose decoder Whh ---------------------------
__global__ __launch_bounds__(1024) void transpose_dec_w(const float* __restrict__ dWhh)
{
    __shared__ float t[32][33];
    const int g  = blockIdx.z;
    const int k0 = blockIdx.x * 32;
    const int u0 = blockIdx.y * 32;
    const int tx = threadIdx.x & 31, ty = threadIdx.x >> 5;
    t[ty][tx] = dWhh[(size_t)(g * 2 * HDIM + u0 + ty) * (2 * HDIM) + k0 + tx];
    __syncthreads();
    g_dWt4[k0 + ty][u0 + tx][g] = t[tx][ty];
}

// ---------------- kernel 1: embedding gather + tanh, time-major -------------
__global__ void embed_kernel(const int* __restrict__ seq, const float* __restrict__ embW) {
    long long idx = (long long)blockIdx.x * blockDim.x + threadIdx.x;
    const long long total = (long long)S_LEN * BSZ * EDIM;
    if (idx >= total) return;
    int e = (int)(idx % EDIM);
    int r = (int)(idx / EDIM);
    int b = r % BSZ;
    int s = r / BSZ;
    int v = seq[b * S_LEN + s];
    g_seq_emb[idx] = tanhf_(embW[(long long)v * EDIM + e]);
}

// ---------------- kernel 2: input GEMMs, double-buffered smem ---------------
__global__ __launch_bounds__(256) void gx_gemm_kernel(
    const float* __restrict__ fWih, const float* __restrict__ fbih, const float* __restrict__ fbhh,
    const float* __restrict__ bWih, const float* __restrict__ bbih, const float* __restrict__ bbhh)
{
    __shared__ float As[2][16][128];
    __shared__ float Bs[2][16][128];

    const int dir   = blockIdx.z;
    const int s     = blockIdx.x;
    const int ntile = blockIdx.y;
    const float* W  = dir ? bWih : fWih;
    const float* bi = dir ? bbih : fbih;
    const float* bh = dir ? bbhh : fbhh;
    const int src_s = dir ? ((S_LEN - s) & (S_LEN - 1)) : s;
    const float* Abase = g_seq_emb + (size_t)src_s * BSZ * EDIM;

    const int t   = threadIdx.x;
    const int lr  = t & 127;
    const int lqp = t >> 7;
    const int tm  = t >> 4;
    const int tn  = t & 15;

    unsigned long long acc2[8][4];
#pragma unroll
    for (int i = 0; i < 8; i++)
#pragma unroll
        for (int j = 0; j < 4; j++) acc2[i][j] = 0ULL;

    const int NK = (EDIM + 15) / 16;   // 19
    float4 av[2], bv[2];
#pragma unroll
    for (int q = 0; q < 2; q++) {
        const int kk = (lqp * 2 + q) * 4;
        av[q] = make_float4(0.f, 0.f, 0.f, 0.f);
        bv[q] = make_float4(0.f, 0.f, 0.f, 0.f);
        if (kk + 3 < EDIM) {
            av[q] = *(const float4*)(W + (size_t)(ntile * 128 + lr) * EDIM + kk);
            bv[q] = *(const float4*)(Abase + (size_t)lr * EDIM + kk);
        }
    }
#pragma unroll
    for (int q = 0; q < 2; q++) {
        const int kb = (lqp * 2 + q) * 4;
        As[0][kb + 0][lr] = av[q].x; As[0][kb + 1][lr] = av[q].y;
        As[0][kb + 2][lr] = av[q].z; As[0][kb + 3][lr] = av[q].w;
        Bs[0][kb + 0][lr] = bv[q].x; Bs[0][kb + 1][lr] = bv[q].y;
        Bs[0][kb + 2][lr] = bv[q].z; Bs[0][kb + 3][lr] = bv[q].w;
    }

    for (int kt = 0; kt < NK; kt++) {
        __syncthreads();
        const int cur = kt & 1;
        const bool more = (kt + 1 < NK);
        if (more) {
#pragma unroll
            for (int q = 0; q < 2; q++) {
                const int kk = (kt + 1) * 16 + (lqp * 2 + q) * 4;
                av[q] = make_float4(0.f, 0.f, 0.f, 0.f);
                bv[q] = make_float4(0.f, 0.f, 0.f, 0.f);
                if (kk + 3 < EDIM) {
                    av[q] = *(const float4*)(W + (size_t)(ntile * 128 + lr) * EDIM + kk);
                    bv[q] = *(const float4*)(Abase + (size_t)lr * EDIM + kk);
                }
            }
        }
#pragma unroll
        for (int k = 0; k < 16; k++) {
            float4 aA = *(const float4*)&As[cur][k][tm * 8];
            float4 aB = *(const float4*)&As[cur][k][tm * 8 + 4];
            ulonglong2 bA = *(const ulonglong2*)&Bs[cur][k][4 * tn];
            ulonglong2 bB = *(const ulonglong2*)&Bs[cur][k][64 + 4 * tn];
            unsigned long long a[8];
            a[0] = pk2(aA.x, aA.x); a[1] = pk2(aA.y, aA.y);
            a[2] = pk2(aA.z, aA.z); a[3] = pk2(aA.w, aA.w);
            a[4] = pk2(aB.x, aB.x); a[5] = pk2(aB.y, aB.y);
            a[6] = pk2(aB.z, aB.z); a[7] = pk2(aB.w, aB.w);
#pragma unroll
            for (int i = 0; i < 8; i++) {
                fma2(acc2[i][0], a[i], bA.x);
                fma2(acc2[i][1], a[i], bA.y);
                fma2(acc2[i][2], a[i], bB.x);
                fma2(acc2[i][3], a[i], bB.y);
            }
        }
        if (more) {
            const int nxt = cur ^ 1;
#pragma unroll
            for (int q = 0; q < 2; q++) {
                const int kb = (lqp * 2 + q) * 4;
                As[nxt][kb + 0][lr] = av[q].x; As[nxt][kb + 1][lr] = av[q].y;
                As[nxt][kb + 2][lr] = av[q].z; As[nxt][kb + 3][lr] = av[q].w;
                Bs[nxt][kb + 0][lr] = bv[q].x; Bs[nxt][kb + 1][lr] = bv[q].y;
                Bs[nxt][kb + 2][lr] = bv[q].z; Bs[nxt][kb + 3][lr] = bv[q].w;
            }
        }
    }
    float* gbase = g_gx[dir] + (size_t)s * 1024 * 128;
#pragma unroll
    for (int i = 0; i < 8; i++) {
        const int col = ntile * 128 + tm * 8 + i;
        const float bb = bi[col] + bh[col];
        float2 v0 = upk2(acc2[i][0]), v1 = upk2(acc2[i][1]);
        float2 v2 = upk2(acc2[i][2]), v3 = upk2(acc2[i][3]);
        float4 oA = make_float4(v0.x + bb, v0.y + bb, v1.x + bb, v1.y + bb);
        float4 oB = make_float4(v2.x + bb, v2.y + bb, v3.x + bb, v3.y + bb);
        *(float4*)(gbase + (size_t)col * 128 + 4 * tn)      = oA;
        *(float4*)(gbase + (size_t)col * 128 + 64 + 4 * tn) = oB;
    }
}

// ---------------- kernel 3: ONE LSTM STEP (hardware sync = kernel boundary) -
// Grid 128 CTAs x 512 threads: CTA = (dir, 4-unit slice). Warp w: ks=w>>3
// (k half), wb=w&7 (batch group). Lane: ul=l>>3 (unit), bp=l&7 (2 batches).
// Weights restaged to smem from hot L2 each step; c persists in g_c; h
// ping-pongs through L2. s==0 skips the h loop (h==0) and uses c=0.
__global__ __launch_bounds__(512) void lstm_step_kernel(int s)
{
    __shared__ unsigned long long wd[HDIM][4][4];   // dup'd weight pairs, 32KB
    __shared__ unsigned long long part[8][32][4];   // kslice-1 partials, 8KB

    const int cta = blockIdx.x;
    const int dir = cta >> 6;
    const int cl  = cta & 63;
    const int u0  = cl * 4;
    const int t   = threadIdx.x;
    const int w   = t >> 5;
    const int l   = t & 31;
    const int ks  = w >> 3;             // k slice 0/1
    const int wb  = w & 7;              // batch group
    const int ul  = l >> 3;             // unit 0..3
    const int bp  = l & 7;              // batch pair
    const int u   = u0 + ul;
    const int b0  = wb * 16 + 2 * bp;
    const int kbase = ks * 128;
    const int buf = s & 1;

    // gx + c loads issued first (DRAM/L2 latency overlapped with weight staging)
    const float* gxd = g_gx[dir];
    float2 gxq[4];
    float2 cc = make_float2(0.f, 0.f);
    if (ks == 0) {
#pragma unroll
        for (int g = 0; g < 4; g++)
            gxq[g] = __ldcg((const float2*)(gxd + ((size_t)s * 1024 + g * 256 + u) * 128 + b0));
        if (s > 0) cc = __ldcg((const float2*)&g_c[dir][u][b0]);
    }

    // stage dup'd weights (16KB from L2 -> 32KB smem)
    for (int e = t; e < 256 * 16; e += 512) {
        int k = e >> 4, ui = (e >> 2) & 3, g = e & 3;
        float wv = g_Wt4[dir][k][u0 + ui][g];
        wd[k][ui][g] = pk2(wv, wv);
    }
    __syncthreads();

    unsigned long long acc[4] = {0ULL, 0ULL, 0ULL, 0ULL};
    if (s > 0) {
        const float* hb = &g_h[dir][buf][0][0] + kbase * 128 + b0;
        unsigned long long hpA[8], hpB[8];
#pragma unroll
        for (int i = 0; i < 8; i++) hpA[i] = __ldcg((const unsigned long long*)(hb + i * 128));
#pragma unroll
        for (int i = 0; i < 8; i++) hpB[i] = __ldcg((const unsigned long long*)(hb + (8 + i) * 128));

        for (int kc = 0; kc < 16; kc += 2) {
            const int kA = kbase + kc * 8, kB = kA + 8;
#pragma unroll
            for (int i = 0; i < 8; i++) {
                ulonglong2 wif = *(const ulonglong2*)&wd[kA + i][ul][0];
                ulonglong2 wgo = *(const ulonglong2*)&wd[kA + i][ul][2];
                fma2(acc[0], wif.x, hpA[i]); fma2(acc[1], wif.y, hpA[i]);
                fma2(acc[2], wgo.x, hpA[i]); fma2(acc[3], wgo.y, hpA[i]);
            }
            if (kc + 2 < 16) {
                const float* src = hb + (kc + 2) * 8 * 128;
#pragma unroll
                for (int i = 0; i < 8; i++) hpA[i] = __ldcg((const unsigned long long*)(src + i * 128));
            }
#pragma unroll
            for (int i = 0; i < 8; i++) {
                ulonglong2 wif = *(const ulonglong2*)&wd[kB + i][ul][0];
                ulonglong2 wgo = *(const ulonglong2*)&wd[kB + i][ul][2];
                fma2(acc[0], wif.x, hpB[i]); fma2(acc[1], wif.y, hpB[i]);
                fma2(acc[2], wgo.x, hpB[i]); fma2(acc[3], wgo.y, hpB[i]);
            }
            if (kc + 3 < 16) {
                const float* src = hb + (kc + 3) * 8 * 128;
#pragma unroll
                for (int i = 0; i < 8; i++) hpB[i] = __ldcg((const unsigned long long*)(src + i * 128));
            }
        }
    }
    if (ks == 1) {
        *(ulonglong2*)&part[wb][l][0] = make_ulonglong2(acc[0], acc[1]);
        *(ulonglong2*)&part[wb][l][2] = make_ulonglong2(acc[2], acc[3]);
    }
    __syncthreads();
    if (ks == 0) {
        ulonglong2 p01 = *(const ulonglong2*)&part[wb][l][0];
        ulonglong2 p23 = *(const ulonglong2*)&part[wb][l][2];
        add2(acc[0], p01.x); add2(acc[1], p01.y);
        add2(acc[2], p23.x); add2(acc[3], p23.y);
        float2 vi = upk2(acc[0]), vf = upk2(acc[1]), vg = upk2(acc[2]), vo = upk2(acc[3]);
        float h0v, h1v;
        {
            float gi = gxq[0].x + vi.x, gf = gxq[1].x + vf.x;
            float gg = gxq[2].x + vg.x, go = gxq[3].x + vo.x;
            float c2 = sigmoidf_(gf) * cc.x + sigmoidf_(gi) * tanhf_(gg);
            cc.x = c2; h0v = sigmoidf_(go) * tanhf_(c2);
        }
        {
            float gi = gxq[0].y + vi.y, gf = gxq[1].y + vf.y;
            float gg = gxq[2].y + vg.y, go = gxq[3].y + vo.y;
            float c2 = sigmoidf_(gf) * cc.y + sigmoidf_(gi) * tanhf_(gg);
            cc.y = c2; h1v = sigmoidf_(go) * tanhf_(c2);
        }
        __stcg((float2*)&g_h[dir][buf ^ 1][u][b0], make_float2(h0v, h1v));
        __stcg((float2*)&g_c[dir][u][b0], cc);
        if (s == S_LEN - 1) {
            g_h0[(size_t)b0 * (2 * HDIM) + dir * HDIM + u]       = h0v;
            g_h0[(size_t)(b0 + 1) * (2 * HDIM) + dir * HDIM + u] = h1v;
        }
    }
}

// ---------------- kernel 4: decoder input gates ------------------------------
__global__ __launch_bounds__(256) void dec_prep_kernel(
    const int* __restrict__ classes, const float* __restrict__ ecW,
    const float* __restrict__ dWih, const float* __restrict__ dbih)
{
    __shared__ float ce[EDIM];
    const int c = blockIdx.x;
    const int cls = classes[c];
    for (int e = threadIdx.x; e < EDIM; e += blockDim.x)
        ce[e] = tanhf_(ecW[(size_t)cls * EDIM + e]);
    __syncthreads();
    const int j = blockIdx.y * 256 + threadIdx.x;
    float acc = dbih[j];
    const float4* w = (const float4*)(dWih + (size_t)j * EDIM);
#pragma unroll 5
    for (int k = 0; k < EDIM / 4; k++) {
        float4 wv = w[k];
        acc += wv.x * ce[4 * k] + wv.y * ce[4 * k + 1] + wv.z * ce[4 * k + 2] + wv.w * ce[4 * k + 3];
    }
    g_gxc[c * 1536 + j] = acc;
}

// ---------------- kernel 5: decoder GRU + proj + cls + log_softmax ----------
__global__ __launch_bounds__(512) void dec_kernel(
    const float* __restrict__ dbhh,
    const float* __restrict__ projW, const float* __restrict__ projB,
    const float* __restrict__ clsW, const float* __restrict__ clsB,
    float* __restrict__ out)
{
    const int Gd = 2;
    const int H2 = 2 * HDIM;
    const int b0 = blockIdx.x * Gd;
    const int u  = threadIdx.x;
    const ulonglong2* W2 = (const ulonglong2*)&g_dWt4[0][0][0];

    __shared__ unsigned long long hd[2][Gd][512];
    __shared__ float hplain[Gd][512];
    __shared__ float projs[Gd][PDIM];
    __shared__ float lgs[Gd][2];

    float hprev[Gd];
#pragma unroll
    for (int b = 0; b < Gd; b++) {
        hprev[b] = g_h0[(size_t)(b0 + b) * H2 + u];
        hd[0][b][u] = pk2(hprev[b], hprev[b]);
    }
    const float bhr = dbhh[u], bhz = dbhh[H2 + u], bhn = dbhh[2 * H2 + u];
    __syncthreads();

    for (int c = 0; c < NCLS; c++) {
        const int cur = c & 1, nxt = cur ^ 1;
        unsigned long long arz[Gd], anp[Gd];
#pragma unroll
        for (int b = 0; b < Gd; b++) { arz[b] = 0ULL; anp[b] = 0ULL; }
        const unsigned long long* h0p = &hd[cur][0][0];
        const unsigned long long* h1p = &hd[cur][1][0];

#pragma unroll 4
        for (int k = 0; k < H2; k++) {
            ulonglong2 wv = W2[k * H2 + u];
            unsigned long long hh0 = h0p[k], hh1 = h1p[k];
            fma2(arz[0], wv.x, hh0); fma2(anp[0], wv.y, hh0);
            fma2(arz[1], wv.x, hh1); fma2(anp[1], wv.y, hh1);
        }
        const float gxr = g_gxc[c * 1536 + u];
        const float gxz = g_gxc[c * 1536 + H2 + u];
        const float gxn = g_gxc[c * 1536 + 2 * H2 + u];
#pragma unroll
        for (int b = 0; b < Gd; b++) {
            float2 vrz = upk2(arz[b]);
            float2 vnp = upk2(anp[b]);
            float r = sigmoidf_(gxr + vrz.x + bhr);
            float z = sigmoidf_(gxz + vrz.y + bhz);
            float n = tanhf_(gxn + r * (vnp.x + bhn));
            float hn = tanhf_((1.0f - z) * n + z * hprev[b]);
            hprev[b] = hn;
            hd[nxt][b][u] = pk2(hn, hn);
            hplain[b][u] = hn;
        }
        __syncthreads();
        {
            const int b = u >> 8, p = u & 255;
            const float4* wv = (const float4*)(projW + (size_t)p * H2);
            const float4* hv = (const float4*)hplain[b];
            float acc = projB[p];
            for (int k4 = 0; k4 < H2 / 4; k4++) {
                float4 w4 = wv[k4], h4 = hv[k4];
                acc += w4.x * h4.x + w4.y * h4.y + w4.z * h4.z + w4.w * h4.w;
            }
            projs[b][p] = acc;
        }
        __syncthreads();
        const int wid = u >> 5, lid = u & 31;
        if (wid < Gd * 2) {
            const int b = wid >> 1, cl = wid & 1;
            float acc = 0.0f;
            for (int k = lid; k < PDIM; k += 32) acc += clsW[cl * PDIM + k] * projs[b][k];
#pragma unroll
            for (int o = 16; o > 0; o >>= 1) acc += __shfl_down_sync(0xffffffffu, acc, o);
            if (lid == 0) lgs[b][cl] = acc + clsB[cl];
        }
        __syncthreads();
        if (u < Gd) {
            const int b = u;
            float l0 = lgs[b][0], l1 = lgs[b][1];
            float m = fmaxf(l0, l1);
            float lse = m + logf(expf(l0 - m) + expf(l1 - m));
            out[(size_t)c * BSZ * 2 + (b0 + b) * 2 + 0] = l0 - lse;
            out[(size_t)c * BSZ * 2 + (b0 + b) * 2 + 1] = l1 - lse;
        }
        __syncthreads();
    }
}

// ---------------- launch -----------------------------------------------------
extern "C" void kernel_launch(void* const* d_in, const int* in_sizes, int n_in,
                              void* d_out, int out_size)
{
    const int*   seq     = (const int*)d_in[0];
    const int*   classes = (const int*)d_in[1];
    const float* embW    = (const float*)d_in[2];
    const float* ecW     = (const float*)d_in[3];
    const float* fWih    = (const float*)d_in[4];
    const float* fWhh    = (const float*)d_in[5];
    const float* fbih    = (const float*)d_in[6];
    const float* fbhh    = (const float*)d_in[7];
    const float* bWih    = (const float*)d_in[8];
    const float* bWhh    = (const float*)d_in[9];
    const float* bbih    = (const float*)d_in[10];
    const float* bbhh    = (const float*)d_in[11];
    const float* dWih    = (const float*)d_in[12];
    const float* dWhh    = (const float*)d_in[13];
    const float* dbih    = (const float*)d_in[14];
    const float* dbhh    = (const float*)d_in[15];
    const float* projW   = (const float*)d_in[16];
    const float* projB   = (const float*)d_in[17];
    const float* clsW    = (const float*)d_in[18];
    const float* clsB    = (const float*)d_in[19];
    float* out = (float*)d_out;

    {   // 0. weight transposes
        dim3 gl(HDIM / 32, HDIM / 32, 8);
        transpose_lstm_w<<<gl, 1024>>>(fWhh, bWhh);
        dim3 gd(2 * HDIM / 32, 2 * HDIM / 32, 3);
        transpose_dec_w<<<gd, 1024>>>(dWhh);
    }
    {   // 1. embeddings
        long long total = (long long)S_LEN * BSZ * EDIM;
        int blocks = (int)((total + 255) / 256);
        embed_kernel<<<blocks, 256>>>(seq, embW);
    }
    {   // 2. input-gate GEMMs, double-buffered
        dim3 grid(S_LEN, 1024 / 128, 2);
        gx_gemm_kernel<<<grid, 256>>>(fWih, fbih, fbhh, bWih, bbih, bbhh);
    }
    {   // 3. LSTM: one kernel node per time step (graph-replayed chain)
        for (int s = 0; s < S_LEN; s++)
            lstm_step_kernel<<<128, 512>>>(s);
    }
    {   // 4. decoder input gates per class
        dim3 grid(NCLS, 6);
        dec_prep_kernel<<<grid, 256>>>(classes, ecW, dWih, dbih);
    }
    {   // 5. decoder GRU + projection + classifier + log_softmax
        dec_kernel<<<BSZ / 2, 512>>>(dbhh, projW, projB, clsW, clsB, out);
    }
    (void)in_sizes; (void)n_in; (void)out_size;
}

// round 11
// speedup vs baseline: 1.3875x; 1.0977x over previous
#include <cuda_runtime.h>
#include <cuda_bf16.h>
#include <math.h>

#define S_LEN 512
#define BSZ   128
#define EDIM  300
#define HDIM  256
#define NCLS  6
#define PDIM  256
#define NCTA_LSTM 128            // 64 u-slice CTAs per direction

// ---------------- scratch (device globals; no runtime allocation) ----------
__device__ float g_seq_emb[(size_t)S_LEN * BSZ * EDIM];              // 78.6 MB
__device__ float g_gx[2][(size_t)S_LEN * 4 * HDIM * BSZ];            // [dir][s][col][b] 536 MB
__device__ float g_h[2][2][HDIM][BSZ];                               // [dir][buf][u][b]
__device__ float g_h0[(size_t)BSZ * 2 * HDIM];                       // concat [fh, bh]
__device__ float g_gxc[NCLS * 3 * 2 * HDIM];                         // decoder input gates
__device__ float g_Wt4[2][HDIM][HDIM][4];                            // [dir][k][u][gate i,f,g,o]
__device__ float g_dWt4[2 * HDIM][2 * HDIM][4];                      // [k][u][gate r,z,n,pad]
__device__ int   g_cnt[2][2][32];                                    // [dir][chain] arrival counters (padded)
__device__ volatile int g_cflags[2][2][64][32];                      // [dir][chain][cta] release lines

// ---------------- helpers ---------------------------------------------------
__device__ __forceinline__ float sigmoidf_(float x) { return 1.0f / (1.0f + expf(-x)); }
__device__ __forceinline__ float tanhf_(float x) { return 1.0f - 2.0f / (expf(2.0f * x) + 1.0f); }

__device__ __forceinline__ unsigned long long pk2(float lo, float hi) {
    return ((unsigned long long)__float_as_uint(hi) << 32) | (unsigned long long)__float_as_uint(lo);
}
__device__ __forceinline__ float2 upk2(unsigned long long u) {
    float2 f; f.x = __uint_as_float((unsigned)u); f.y = __uint_as_float((unsigned)(u >> 32)); return f;
}
__device__ __forceinline__ void fma2(unsigned long long& d, unsigned long long a, unsigned long long b) {
    asm("fma.rn.f32x2 %0, %1, %2, %0;" : "+l"(d) : "l"(a), "l"(b));
}
__device__ __forceinline__ void add2(unsigned long long& d, unsigned long long a) {
    asm("add.rn.f32x2 %0, %0, %1;" : "+l"(d) : "l"(a));
}
__device__ __forceinline__ void named_bar(int id) {
    asm volatile("bar.sync %0, 256;" :: "r"(id) : "memory");
}

// ---------------- kernel 0a: transpose LSTM Whh + reset barriers ------------
__global__ __launch_bounds__(1024) void transpose_lstm_w(const float* __restrict__ fWhh,
                                                         const float* __restrict__ bWhh)
{
    if (blockIdx.x == 0 && blockIdx.y == 0 && blockIdx.z == 0) {
        for (int i = threadIdx.x; i < 2 * 2 * 32; i += 1024) ((int*)g_cnt)[i] = 0;
        for (int i = threadIdx.x; i < 2 * 2 * 64 * 32; i += 1024) ((int*)g_cflags)[i] = 0;
    }
    __shared__ float t[32][33];
    const int dir = blockIdx.z >> 2;
    const int g   = blockIdx.z & 3;
    const int k0  = blockIdx.x * 32;
    const int u0  = blockIdx.y * 32;
    const int tx = threadIdx.x & 31, ty = threadIdx.x >> 5;
    const float* W = dir ? bWhh : fWhh;
    t[ty][tx] = W[(size_t)(g * HDIM + u0 + ty) * HDIM + k0 + tx];
    __syncthreads();
    g_Wt4[dir][k0 + ty][u0 + tx][g] = t[tx][ty];
}

// ---------------- kernel 0b: transpose decoder Whh ---------------------------
__global__ __launch_bounds__(1024) void transpose_dec_w(const float* __restrict__ dWhh)
{
    __shared__ float t[32][33];
    const int g  = blockIdx.z;
    const int k0 = blockIdx.x * 32;
    const int u0 = blockIdx.y * 32;
    const int tx = threadIdx.x & 31, ty = threadIdx.x >> 5;
    t[ty][tx] = dWhh[(size_t)(g * 2 * HDIM + u0 + ty) * (2 * HDIM) + k0 + tx];
    __syncthreads();
    g_dWt4[k0 + ty][u0 + tx][g] = t[tx][ty];
}

// ---------------- kernel 1: embedding gather + tanh, time-major -------------
__global__ void embed_kernel(const int* __restrict__ seq, const float* __restrict__ embW) {
    long long idx = (long long)blockIdx.x * blockDim.x + threadIdx.x;
    const long long total = (long long)S_LEN * BSZ * EDIM;
    if (idx >= total) return;
    int e = (int)(idx % EDIM);
    int r = (int)(idx / EDIM);
    int b = r % BSZ;
    int s = r / BSZ;
    int v = seq[b * S_LEN + s];
    g_seq_emb[idx] = tanhf_(embW[(long long)v * EDIM + e]);
}

// ---------------- kernel 2: input GEMMs, double-buffered smem ---------------
__global__ __launch_bounds__(256) void gx_gemm_kernel(
    const float* __restrict__ fWih, const float* __restrict__ fbih, const float* __restrict__ fbhh,
    const float* __restrict__ bWih, const float* __restrict__ bbih, const float* __restrict__ bbhh)
{
    __shared__ float As[2][16][128];
    __shared__ float Bs[2][16][128];

    const int dir   = blockIdx.z;
    const int s     = blockIdx.x;
    const int ntile = blockIdx.y;
    const float* W  = dir ? bWih : fWih;
    const float* bi = dir ? bbih : fbih;
    const float* bh = dir ? bbhh : fbhh;
    const int src_s = dir ? ((S_LEN - s) & (S_LEN - 1)) : s;
    const float* Abase = g_seq_emb + (size_t)src_s * BSZ * EDIM;

    const int t   = threadIdx.x;
    const int lr  = t & 127;
    const int lqp = t >> 7;
    const int tm  = t >> 4;
    const int tn  = t & 15;

    unsigned long long acc2[8][4];
#pragma unroll
    for (int i = 0; i < 8; i++)
#pragma unroll
        for (int j = 0; j < 4; j++) acc2[i][j] = 0ULL;

    const int NK = (EDIM + 15) / 16;   // 19
    float4 av[2], bv[2];
#pragma unroll
    for (int q = 0; q < 2; q++) {
        const int kk = (lqp * 2 + q) * 4;
        av[q] = make_float4(0.f, 0.f, 0.f, 0.f);
        bv[q] = make_float4(0.f, 0.f, 0.f, 0.f);
        if (kk + 3 < EDIM) {
            av[q] = *(const float4*)(W + (size_t)(ntile * 128 + lr) * EDIM + kk);
            bv[q] = *(const float4*)(Abase + (size_t)lr * EDIM + kk);
        }
    }
#pragma unroll
    for (int q = 0; q < 2; q++) {
        const int kb = (lqp * 2 + q) * 4;
        As[0][kb + 0][lr] = av[q].x; As[0][kb + 1][lr] = av[q].y;
        As[0][kb + 2][lr] = av[q].z; As[0][kb + 3][lr] = av[q].w;
        Bs[0][kb + 0][lr] = bv[q].x; Bs[0][kb + 1][lr] = bv[q].y;
        Bs[0][kb + 2][lr] = bv[q].z; Bs[0][kb + 3][lr] = bv[q].w;
    }

    for (int kt = 0; kt < NK; kt++) {
        __syncthreads();
        const int cur = kt & 1;
        const bool more = (kt + 1 < NK);
        if (more) {
#pragma unroll
            for (int q = 0; q < 2; q++) {
                const int kk = (kt + 1) * 16 + (lqp * 2 + q) * 4;
                av[q] = make_float4(0.f, 0.f, 0.f, 0.f);
                bv[q] = make_float4(0.f, 0.f, 0.f, 0.f);
                if (kk + 3 < EDIM) {
                    av[q] = *(const float4*)(W + (size_t)(ntile * 128 + lr) * EDIM + kk);
                    bv[q] = *(const float4*)(Abase + (size_t)lr * EDIM + kk);
                }
            }
        }
#pragma unroll
        for (int k = 0; k < 16; k++) {
            float4 aA = *(const float4*)&As[cur][k][tm * 8];
            float4 aB = *(const float4*)&As[cur][k][tm * 8 + 4];
            ulonglong2 bA = *(const ulonglong2*)&Bs[cur][k][4 * tn];
            ulonglong2 bB = *(const ulonglong2*)&Bs[cur][k][64 + 4 * tn];
            unsigned long long a[8];
            a[0] = pk2(aA.x, aA.x); a[1] = pk2(aA.y, aA.y);
            a[2] = pk2(aA.z, aA.z); a[3] = pk2(aA.w, aA.w);
            a[4] = pk2(aB.x, aB.x); a[5] = pk2(aB.y, aB.y);
            a[6] = pk2(aB.z, aB.z); a[7] = pk2(aB.w, aB.w);
#pragma unroll
            for (int i = 0; i < 8; i++) {
                fma2(acc2[i][0], a[i], bA.x);
                fma2(acc2[i][1], a[i], bA.y);
                fma2(acc2[i][2], a[i], bB.x);
                fma2(acc2[i][3], a[i], bB.y);
            }
        }
        if (more) {
            const int nxt = cur ^ 1;
#pragma unroll
            for (int q = 0; q < 2; q++) {
                const int kb = (lqp * 2 + q) * 4;
                As[nxt][kb + 0][lr] = av[q].x; As[nxt][kb + 1][lr] = av[q].y;
                As[nxt][kb + 2][lr] = av[q].z; As[nxt][kb + 3][lr] = av[q].w;
                Bs[nxt][kb + 0][lr] = bv[q].x; Bs[nxt][kb + 1][lr] = bv[q].y;
                Bs[nxt][kb + 2][lr] = bv[q].z; Bs[nxt][kb + 3][lr] = bv[q].w;
            }
        }
    }
    float* gbase = g_gx[dir] + (size_t)s * 1024 * 128;
#pragma unroll
    for (int i = 0; i < 8; i++) {
        const int col = ntile * 128 + tm * 8 + i;
        const float bb = bi[col] + bh[col];
        float2 v0 = upk2(acc2[i][0]), v1 = upk2(acc2[i][1]);
        float2 v2 = upk2(acc2[i][2]), v3 = upk2(acc2[i][3]);
        float4 oA = make_float4(v0.x + bb, v0.y + bb, v1.x + bb, v1.y + bb);
        float4 oB = make_float4(v2.x + bb, v2.y + bb, v3.x + bb, v3.y + bb);
        *(float4*)(gbase + (size_t)col * 128 + 4 * tn)      = oA;
        *(float4*)(gbase + (size_t)col * 128 + 64 + 4 * tn) = oB;
    }
}

// ---------------- kernel 3: persistent LSTM, TWO independent chains ---------
// 128 CTAs x 512 threads. CTA = (dir, 4-unit slice). Warps 0-7 = chain A
// (batches 0-63), warps 8-15 = chain B (batches 64-127). Each chain: 4 batch
// groups x 2 k-slices, named-barrier synced (bar 1 / bar 2), with its OWN
// global barrier (counter+flags per (dir,chain)). While one chain waits at
// its barrier, the other chain's 2 warps/SMSP saturate the FFMA2 pipe.
__global__ __launch_bounds__(512) void lstm_persist()
{
    __shared__ unsigned long long wd[HDIM][4][4];     // dup'd weight pairs, 32KB
    __shared__ unsigned long long part[2][4][32][4];  // [chain][wb][lane][g] partials, 8KB

    const int cta = blockIdx.x;
    const int dir = cta >> 6;
    const int cl  = cta & 63;
    const int u0  = cl * 4;
    const int t   = threadIdx.x;
    const int w   = t >> 5;
    const int l   = t & 31;
    const int ch  = w >> 3;             // chain 0/1
    const int wc  = w & 7;              // warp within chain
    const int ks  = wc >> 2;            // k slice 0/1
    const int wb  = wc & 3;             // batch group in chain
    const int ul  = l >> 3;             // unit 0..3
    const int bp  = l & 7;              // batch pair
    const int u   = u0 + ul;
    const int b0  = ch * 64 + wb * 16 + 2 * bp;
    const int kbase = ks * 128;
    const int barid = ch + 1;

    // stage dup'd weights (shared by both chains)
    for (int e = t; e < 256 * 16; e += 512) {
        int k = e >> 4, ui = (e >> 2) & 3, g = e & 3;
        float wv = g_Wt4[dir][k][u0 + ui][g];
        wd[k][ui][g] = pk2(wv, wv);
    }
    float c0 = 0.f, c1 = 0.f, h0v = 0.f, h1v = 0.f;
    if (ks == 0) {
        *(float2*)&g_h[dir][0][u][b0] = make_float2(0.f, 0.f);
        __threadfence();
    }
    __syncthreads();

    int ep = 1;
    // initial chain barrier (h zeros visible across the chain's 64 CTAs)
    if (wc == 0) {
        int v = 0;
        if (l == 0) v = atomicAdd(&g_cnt[dir][ch][0], 1);
        v = __shfl_sync(0xffffffffu, v, 0);
        if (v == ep * 64 - 1) {
            g_cflags[dir][ch][l][0] = ep;
            g_cflags[dir][ch][l + 32][0] = ep;
        } else if (l == 0) {
            while (g_cflags[dir][ch][cl][0] < ep) { }
            __threadfence();
        }
    }
    named_bar(barid);

    const float* gxd = g_gx[dir];
    float2 gxq[4];
    if (ks == 0) {
#pragma unroll
        for (int g = 0; g < 4; g++)
            gxq[g] = __ldcg((const float2*)(gxd + ((size_t)0 * 1024 + g * 256 + u) * 128 + b0));
    }

    for (int s = 0; s < S_LEN; s++) {
        const int buf = s & 1;
        const float* hb = &g_h[dir][buf][0][0] + kbase * 128 + b0;

        unsigned long long acc[4] = {0ULL, 0ULL, 0ULL, 0ULL};
        unsigned long long hpA[8], hpB[8];
#pragma unroll
        for (int i = 0; i < 8; i++) hpA[i] = __ldcg((const unsigned long long*)(hb + i * 128));
#pragma unroll
        for (int i = 0; i < 8; i++) hpB[i] = __ldcg((const unsigned long long*)(hb + (8 + i) * 128));

        for (int kc = 0; kc < 16; kc += 2) {
            const int kA = kbase + kc * 8, kB = kA + 8;
#pragma unroll
            for (int i = 0; i < 8; i++) {
                ulonglong2 wif = *(const ulonglong2*)&wd[kA + i][ul][0];
                ulonglong2 wgo = *(const ulonglong2*)&wd[kA + i][ul][2];
                fma2(acc[0], wif.x, hpA[i]); fma2(acc[1], wif.y, hpA[i]);
                fma2(acc[2], wgo.x, hpA[i]); fma2(acc[3], wgo.y, hpA[i]);
            }
            if (kc + 2 < 16) {
                const float* src = hb + (kc + 2) * 8 * 128;
#pragma unroll
                for (int i = 0; i < 8; i++) hpA[i] = __ldcg((const unsigned long long*)(src + i * 128));
            }
#pragma unroll
            for (int i = 0; i < 8; i++) {
                ulonglong2 wif = *(const ulonglong2*)&wd[kB + i][ul][0];
                ulonglong2 wgo = *(const ulonglong2*)&wd[kB + i][ul][2];
                fma2(acc[0], wif.x, hpB[i]); fma2(acc[1], wif.y, hpB[i]);
                fma2(acc[2], wgo.x, hpB[i]); fma2(acc[3], wgo.y, hpB[i]);
            }
            if (kc + 3 < 16) {
                const float* src = hb + (kc + 3) * 8 * 128;
#pragma unroll
                for (int i = 0; i < 8; i++) hpB[i] = __ldcg((const unsigned long long*)(src + i * 128));
            }
        }
        if (ks == 1) {
            *(ulonglong2*)&part[ch][wb][l][0] = make_ulonglong2(acc[0], acc[1]);
            *(ulonglong2*)&part[ch][wb][l][2] = make_ulonglong2(acc[2], acc[3]);
        }
        named_bar(barid);
        if (ks == 0) {
            ulonglong2 p01 = *(const ulonglong2*)&part[ch][wb][l][0];
            ulonglong2 p23 = *(const ulonglong2*)&part[ch][wb][l][2];
            add2(acc[0], p01.x); add2(acc[1], p01.y);
            add2(acc[2], p23.x); add2(acc[3], p23.y);
            float2 vi = upk2(acc[0]), vf = upk2(acc[1]), vg = upk2(acc[2]), vo = upk2(acc[3]);
            {
                float gi = gxq[0].x + vi.x, gf = gxq[1].x + vf.x;
                float gg = gxq[2].x + vg.x, go = gxq[3].x + vo.x;
                float cc = sigmoidf_(gf) * c0 + sigmoidf_(gi) * tanhf_(gg);
                c0 = cc; h0v = sigmoidf_(go) * tanhf_(cc);
            }
            {
                float gi = gxq[0].y + vi.y, gf = gxq[1].y + vf.y;
                float gg = gxq[2].y + vg.y, go = gxq[3].y + vo.y;
                float cc = sigmoidf_(gf) * c1 + sigmoidf_(gi) * tanhf_(gg);
                c1 = cc; h1v = sigmoidf_(go) * tanhf_(cc);
            }
            __stcg((float2*)&g_h[dir][buf ^ 1][u][b0], make_float2(h0v, h1v));
            if (s + 1 < S_LEN) {
#pragma unroll
                for (int g = 0; g < 4; g++)
                    gxq[g] = __ldcg((const float2*)(gxd + ((size_t)(s + 1) * 1024 + g * 256 + u) * 128 + b0));
            }
            __threadfence();
        }
        named_bar(barid);
        ep++;
        if (wc == 0) {
            int v = 0;
            if (l == 0) v = atomicAdd(&g_cnt[dir][ch][0], 1);
            v = __shfl_sync(0xffffffffu, v, 0);
            if (v == ep * 64 - 1) {
                g_cflags[dir][ch][l][0] = ep;
                g_cflags[dir][ch][l + 32][0] = ep;
            } else if (l == 0) {
                while (g_cflags[dir][ch][cl][0] < ep) { }
                __threadfence();
            }
        }
        named_bar(barid);
    }
    if (ks == 0) {
        g_h0[(size_t)b0 * (2 * HDIM) + dir * HDIM + u]       = h0v;
        g_h0[(size_t)(b0 + 1) * (2 * HDIM) + dir * HDIM + u] = h1v;
    }
}

// ---------------- kernel 4: decoder input gates ------------------------------
__global__ __launch_bounds__(256) void dec_prep_kernel(
    const int* __restrict__ classes, const float* __restrict__ ecW,
    const float* __restrict__ dWih, const float* __restrict__ dbih)
{
    __shared__ float ce[EDIM];
    const int c = blockIdx.x;
    const int cls = classes[c];
    for (int e = threadIdx.x; e < EDIM; e += blockDim.x)
        ce[e] = tanhf_(ecW[(size_t)cls * EDIM + e]);
    __syncthreads();
    const int j = blockIdx.y * 256 + threadIdx.x;
    float acc = dbih[j];
    const float4* w = (const float4*)(dWih + (size_t)j * EDIM);
#pragma unroll 5
    for (int k = 0; k < EDIM / 4; k++) {
        float4 wv = w[k];
        acc += wv.x * ce[4 * k] + wv.y * ce[4 * k + 1] + wv.z * ce[4 * k + 2] + wv.w * ce[4 * k + 3];
    }
    g_gxc[c * 1536 + j] = acc;
}

// ---------------- kernel 5: decoder GRU + proj + cls + log_softmax ----------
__global__ __launch_bounds__(512) void dec_kernel(
    const float* __restrict__ dbhh,
    const float* __restrict__ projW, const float* __restrict__ projB,
    const float* __restrict__ clsW, const float* __restrict__ clsB,
    float* __restrict__ out)
{
    const int Gd = 2;
    const int H2 = 2 * HDIM;
    const int b0 = blockIdx.x * Gd;
    const int u  = threadIdx.x;
    const ulonglong2* W2 = (const ulonglong2*)&g_dWt4[0][0][0];

    __shared__ unsigned long long hd[2][Gd][512];
    __shared__ float hplain[Gd][512];
    __shared__ float projs[Gd][PDIM];
    __shared__ float lgs[Gd][2];

    float hprev[Gd];
#pragma unroll
    for (int b = 0; b < Gd; b++) {
        hprev[b] = g_h0[(size_t)(b0 + b) * H2 + u];
        hd[0][b][u] = pk2(hprev[b], hprev[b]);
    }
    const float bhr = dbhh[u], bhz = dbhh[H2 + u], bhn = dbhh[2 * H2 + u];
    __syncthreads();

    for (int c = 0; c < NCLS; c++) {
        const int cur = c & 1, nxt = cur ^ 1;
        unsigned long long arz[Gd], anp[Gd];
#pragma unroll
        for (int b = 0; b < Gd; b++) { arz[b] = 0ULL; anp[b] = 0ULL; }
        const unsigned long long* h0p = &hd[cur][0][0];
        const unsigned long long* h1p = &hd[cur][1][0];

#pragma unroll 4
        for (int k = 0; k < H2; k++) {
            ulonglong2 wv = W2[k * H2 + u];
            unsigned long long hh0 = h0p[k], hh1 = h1p[k];
            fma2(arz[0], wv.x, hh0); fma2(anp[0], wv.y, hh0);
            fma2(arz[1], wv.x, hh1); fma2(anp[1], wv.y, hh1);
        }
        const float gxr = g_gxc[c * 1536 + u];
        const float gxz = g_gxc[c * 1536 + H2 + u];
        const float gxn = g_gxc[c * 1536 + 2 * H2 + u];
#pragma unroll
        for (int b = 0; b < Gd; b++) {
            float2 vrz = upk2(arz[b]);
            float2 vnp = upk2(anp[b]);
            float r = sigmoidf_(gxr + vrz.x + bhr);
            float z = sigmoidf_(gxz + vrz.y + bhz);
            float n = tanhf_(gxn + r * (vnp.x + bhn));
            float hn = tanhf_((1.0f - z) * n + z * hprev[b]);
            hprev[b] = hn;
            hd[nxt][b][u] = pk2(hn, hn);
            hplain[b][u] = hn;
        }
        __syncthreads();
        {
            const int b = u >> 8, p = u & 255;
            const float4* wv = (const float4*)(projW + (size_t)p * H2);
            const float4* hv = (const float4*)hplain[b];
            float acc = projB[p];
            for (int k4 = 0; k4 < H2 / 4; k4++) {
                float4 w4 = wv[k4], h4 = hv[k4];
                acc += w4.x * h4.x + w4.y * h4.y + w4.z * h4.z + w4.w * h4.w;
            }
            projs[b][p] = acc;
        }
        __syncthreads();
        const int wid = u >> 5, lid = u & 31;
        if (wid < Gd * 2) {
            const int b = wid >> 1, cl = wid & 1;
            float acc = 0.0f;
            for (int k = lid; k < PDIM; k += 32) acc += clsW[cl * PDIM + k] * projs[b][k];
#pragma unroll
            for (int o = 16; o > 0; o >>= 1) acc += __shfl_down_sync(0xffffffffu, acc, o);
            if (lid == 0) lgs[b][cl] = acc + clsB[cl];
        }
        __syncthreads();
        if (u < Gd) {
            const int b = u;
            float l0 = lgs[b][0], l1 = lgs[b][1];
            float m = fmaxf(l0, l1);
            float lse = m + logf(expf(l0 - m) + expf(l1 - m));
            out[(size_t)c * BSZ * 2 + (b0 + b) * 2 + 0] = l0 - lse;
            out[(size_t)c * BSZ * 2 + (b0 + b) * 2 + 1] = l1 - lse;
        }
        __syncthreads();
    }
}

// ---------------- launch -----------------------------------------------------
extern "C" void kernel_launch(void* const* d_in, const int* in_sizes, int n_in,
                              void* d_out, int out_size)
{
    const int*   seq     = (const int*)d_in[0];
    const int*   classes = (const int*)d_in[1];
    const float* embW    = (const float*)d_in[2];
    const float* ecW     = (const float*)d_in[3];
    const float* fWih    = (const float*)d_in[4];
    const float* fWhh    = (const float*)d_in[5];
    const float* fbih    = (const float*)d_in[6];
    const float* fbhh    = (const float*)d_in[7];
    const float* bWih    = (const float*)d_in[8];
    const float* bWhh    = (const float*)d_in[9];
    const float* bbih    = (const float*)d_in[10];
    const float* bbhh    = (const float*)d_in[11];
    const float* dWih    = (const float*)d_in[12];
    const float* dWhh    = (const float*)d_in[13];
    const float* dbih    = (const float*)d_in[14];
    const float* dbhh    = (const float*)d_in[15];
    const float* projW   = (const float*)d_in[16];
    const float* projB   = (const float*)d_in[17];
    const float* clsW    = (const float*)d_in[18];
    const float* clsB    = (const float*)d_in[19];
    float* out = (float*)d_out;

    {   // 0. weight transposes + barrier reset
        dim3 gl(HDIM / 32, HDIM / 32, 8);
        transpose_lstm_w<<<gl, 1024>>>(fWhh, bWhh);
        dim3 gd(2 * HDIM / 32, 2 * HDIM / 32, 3);
        transpose_dec_w<<<gd, 1024>>>(dWhh);
    }
    {   // 1. embeddings
        long long total = (long long)S_LEN * BSZ * EDIM;
        int blocks = (int)((total + 255) / 256);
        embed_kernel<<<blocks, 256>>>(seq, embW);
    }
    {   // 2. input-gate GEMMs, double-buffered
        dim3 grid(S_LEN, 1024 / 128, 2);
        gx_gemm_kernel<<<grid, 256>>>(fWih, fbih, fbhh, bWih, bbih, bbhh);
    }
    {   // 3. persistent bidirectional LSTM, two interleaved chains
        lstm_persist<<<NCTA_LSTM, 512>>>();
    }
    {   // 4. decoder input gates per class
        dim3 grid(NCLS, 6);
        dec_prep_kernel<<<grid, 256>>>(classes, ecW, dWih, dbih);
    }
    {   // 5. decoder GRU + projection + classifier + log_softmax
        dec_kernel<<<BSZ / 2, 512>>>(dbhh, projW, projB, clsW, clsB, out);
    }
    (void)in_sizes; (void)n_in; (void)out_size;
}

// round 12
// speedup vs baseline: 1.4706x; 1.0599x over previous
#include <cuda_runtime.h>
#include <cuda_bf16.h>
#include <math.h>

#define S_LEN 512
#define BSZ   128
#define EDIM  300
#define HDIM  256
#define NCLS  6
#define PDIM  256
#define NCTA_LSTM 128            // 64 u-slice CTAs per direction

// ---------------- scratch (device globals; no runtime allocation) ----------
__device__ float g_seq_emb[(size_t)S_LEN * BSZ * EDIM];              // 78.6 MB
__device__ float g_gx[2][(size_t)S_LEN * 4 * HDIM * BSZ];            // [dir][s][col][b] 536 MB
__device__ float g_h[2][2][HDIM][BSZ];                               // [dir][buf][u][b]
__device__ float g_h0[(size_t)BSZ * 2 * HDIM];                       // concat [fh, bh]
__device__ float g_gxc[NCLS * 3 * 2 * HDIM];                         // decoder input gates
__device__ float g_Wt4[2][HDIM][HDIM][4];                            // [dir][k][u][gate i,f,g,o]
__device__ float g_dWt4[2 * HDIM][2 * HDIM][4];                      // [k][u][gate r,z,n,pad]
// per-CTA progress counters: [dir][chain][cta][pad to 128B] — NO shared atomics
__device__ volatile int g_prog[2][2][64][32];

// ---------------- helpers ---------------------------------------------------
__device__ __forceinline__ float sigmoidf_(float x) { return 1.0f / (1.0f + expf(-x)); }
__device__ __forceinline__ float tanhf_(float x) { return 1.0f - 2.0f / (expf(2.0f * x) + 1.0f); }

__device__ __forceinline__ unsigned long long pk2(float lo, float hi) {
    return ((unsigned long long)__float_as_uint(hi) << 32) | (unsigned long long)__float_as_uint(lo);
}
__device__ __forceinline__ float2 upk2(unsigned long long u) {
    float2 f; f.x = __uint_as_float((unsigned)u); f.y = __uint_as_float((unsigned)(u >> 32)); return f;
}
__device__ __forceinline__ void fma2(unsigned long long& d, unsigned long long a, unsigned long long b) {
    asm("fma.rn.f32x2 %0, %1, %2, %0;" : "+l"(d) : "l"(a), "l"(b));
}
__device__ __forceinline__ void add2(unsigned long long& d, unsigned long long a) {
    asm("add.rn.f32x2 %0, %0, %1;" : "+l"(d) : "l"(a));
}
__device__ __forceinline__ void named_bar(int id) {
    asm volatile("bar.sync %0, 256;" :: "r"(id) : "memory");
}

// ---------------- kernel 0a: transpose LSTM Whh + reset progress ------------
__global__ __launch_bounds__(1024) void transpose_lstm_w(const float* __restrict__ fWhh,
                                                         const float* __restrict__ bWhh)
{
    if (blockIdx.x == 0 && blockIdx.y == 0 && blockIdx.z == 0) {
        for (int i = threadIdx.x; i < 2 * 2 * 64 * 32; i += 1024) ((int*)g_prog)[i] = 0;
    }
    __shared__ float t[32][33];
    const int dir = blockIdx.z >> 2;
    const int g   = blockIdx.z & 3;
    const int k0  = blockIdx.x * 32;
    const int u0  = blockIdx.y * 32;
    const int tx = threadIdx.x & 31, ty = threadIdx.x >> 5;
    const float* W = dir ? bWhh : fWhh;
    t[ty][tx] = W[(size_t)(g * HDIM + u0 + ty) * HDIM + k0 + tx];
    __syncthreads();
    g_Wt4[dir][k0 + ty][u0 + tx][g] = t[tx][ty];
}

// ---------------- kernel 0b: transpose decoder Whh ---------------------------
__global__ __launch_bounds__(1024) void transpose_dec_w(const float* __restrict__ dWhh)
{
    __shared__ float t[32][33];
    const int g  = blockIdx.z;
    const int k0 = blockIdx.x * 32;
    const int u0 = blockIdx.y * 32;
    const int tx = threadIdx.x & 31, ty = threadIdx.x >> 5;
    t[ty][tx] = dWhh[(size_t)(g * 2 * HDIM + u0 + ty) * (2 * HDIM) + k0 + tx];
    __syncthreads();
    g_dWt4[k0 + ty][u0 + tx][g] = t[tx][ty];
}

// ---------------- kernel 1: embedding gather + tanh, time-major -------------
__global__ void embed_kernel(const int* __restrict__ seq, const float* __restrict__ embW) {
    long long idx = (long long)blockIdx.x * blockDim.x + threadIdx.x;
    const long long total = (long long)S_LEN * BSZ * EDIM;
    if (idx >= total) return;
    int e = (int)(idx % EDIM);
    int r = (int)(idx / EDIM);
    int b = r % BSZ;
    int s = r / BSZ;
    int v = seq[b * S_LEN + s];
    g_seq_emb[idx] = tanhf_(embW[(long long)v * EDIM + e]);
}

// ---------------- kernel 2: input GEMMs, double-buffered smem ---------------
__global__ __launch_bounds__(256) void gx_gemm_kernel(
    const float* __restrict__ fWih, const float* __restrict__ fbih, const float* __restrict__ fbhh,
    const float* __restrict__ bWih, const float* __restrict__ bbih, const float* __restrict__ bbhh)
{
    __shared__ float As[2][16][128];
    __shared__ float Bs[2][16][128];

    const int dir   = blockIdx.z;
    const int s     = blockIdx.x;
    const int ntile = blockIdx.y;
    const float* W  = dir ? bWih : fWih;
    const float* bi = dir ? bbih : fbih;
    const float* bh = dir ? bbhh : fbhh;
    const int src_s = dir ? ((S_LEN - s) & (S_LEN - 1)) : s;
    const float* Abase = g_seq_emb + (size_t)src_s * BSZ * EDIM;

    const int t   = threadIdx.x;
    const int lr  = t & 127;
    const int lqp = t >> 7;
    const int tm  = t >> 4;
    const int tn  = t & 15;

    unsigned long long acc2[8][4];
#pragma unroll
    for (int i = 0; i < 8; i++)
#pragma unroll
        for (int j = 0; j < 4; j++) acc2[i][j] = 0ULL;

    const int NK = (EDIM + 15) / 16;   // 19
    float4 av[2], bv[2];
#pragma unroll
    for (int q = 0; q < 2; q++) {
        const int kk = (lqp * 2 + q) * 4;
        av[q] = make_float4(0.f, 0.f, 0.f, 0.f);
        bv[q] = make_float4(0.f, 0.f, 0.f, 0.f);
        if (kk + 3 < EDIM) {
            av[q] = *(const float4*)(W + (size_t)(ntile * 128 + lr) * EDIM + kk);
            bv[q] = *(const float4*)(Abase + (size_t)lr * EDIM + kk);
        }
    }
#pragma unroll
    for (int q = 0; q < 2; q++) {
        const int kb = (lqp * 2 + q) * 4;
        As[0][kb + 0][lr] = av[q].x; As[0][kb + 1][lr] = av[q].y;
        As[0][kb + 2][lr] = av[q].z; As[0][kb + 3][lr] = av[q].w;
        Bs[0][kb + 0][lr] = bv[q].x; Bs[0][kb + 1][lr] = bv[q].y;
        Bs[0][kb + 2][lr] = bv[q].z; Bs[0][kb + 3][lr] = bv[q].w;
    }

    for (int kt = 0; kt < NK; kt++) {
        __syncthreads();
        const int cur = kt & 1;
        const bool more = (kt + 1 < NK);
        if (more) {
#pragma unroll
            for (int q = 0; q < 2; q++) {
                const int kk = (kt + 1) * 16 + (lqp * 2 + q) * 4;
                av[q] = make_float4(0.f, 0.f, 0.f, 0.f);
                bv[q] = make_float4(0.f, 0.f, 0.f, 0.f);
                if (kk + 3 < EDIM) {
                    av[q] = *(const float4*)(W + (size_t)(ntile * 128 + lr) * EDIM + kk);
                    bv[q] = *(const float4*)(Abase + (size_t)lr * EDIM + kk);
                }
            }
        }
#pragma unroll
        for (int k = 0; k < 16; k++) {
            float4 aA = *(const float4*)&As[cur][k][tm * 8];
            float4 aB = *(const float4*)&As[cur][k][tm * 8 + 4];
            ulonglong2 bA = *(const ulonglong2*)&Bs[cur][k][4 * tn];
            ulonglong2 bB = *(const ulonglong2*)&Bs[cur][k][64 + 4 * tn];
            unsigned long long a[8];
            a[0] = pk2(aA.x, aA.x); a[1] = pk2(aA.y, aA.y);
            a[2] = pk2(aA.z, aA.z); a[3] = pk2(aA.w, aA.w);
            a[4] = pk2(aB.x, aB.x); a[5] = pk2(aB.y, aB.y);
            a[6] = pk2(aB.z, aB.z); a[7] = pk2(aB.w, aB.w);
#pragma unroll
            for (int i = 0; i < 8; i++) {
                fma2(acc2[i][0], a[i], bA.x);
                fma2(acc2[i][1], a[i], bA.y);
                fma2(acc2[i][2], a[i], bB.x);
                fma2(acc2[i][3], a[i], bB.y);
            }
        }
        if (more) {
            const int nxt = cur ^ 1;
#pragma unroll
            for (int q = 0; q < 2; q++) {
                const int kb = (lqp * 2 + q) * 4;
                As[nxt][kb + 0][lr] = av[q].x; As[nxt][kb + 1][lr] = av[q].y;
                As[nxt][kb + 2][lr] = av[q].z; As[nxt][kb + 3][lr] = av[q].w;
                Bs[nxt][kb + 0][lr] = bv[q].x; Bs[nxt][kb + 1][lr] = bv[q].y;
                Bs[nxt][kb + 2][lr] = bv[q].z; Bs[nxt][kb + 3][lr] = bv[q].w;
            }
        }
    }
    float* gbase = g_gx[dir] + (size_t)s * 1024 * 128;
#pragma unroll
    for (int i = 0; i < 8; i++) {
        const int col = ntile * 128 + tm * 8 + i;
        const float bb = bi[col] + bh[col];
        float2 v0 = upk2(acc2[i][0]), v1 = upk2(acc2[i][1]);
        float2 v2 = upk2(acc2[i][2]), v3 = upk2(acc2[i][3]);
        float4 oA = make_float4(v0.x + bb, v0.y + bb, v1.x + bb, v1.y + bb);
        float4 oB = make_float4(v2.x + bb, v2.y + bb, v3.x + bb, v3.y + bb);
        *(float4*)(gbase + (size_t)col * 128 + 4 * tn)      = oA;
        *(float4*)(gbase + (size_t)col * 128 + 64 + 4 * tn) = oB;
    }
}

// ---------------- kernel 3: persistent LSTM, two chains, dataflow sync ------
// 128 CTAs x 512 threads. CTA = (dir, 4-unit slice). Warps 0-7 = chain A
// (batches 0-63), warps 8-15 = chain B (batches 64-127); named barriers 1/2.
// SYNC: each CTA publishes its own step counter (1 plain store to its own
// 128B line); one warp per chain polls all 64 producer counters directly.
// Zero same-address atomics, no central release flag.
__global__ __launch_bounds__(512) void lstm_persist()
{
    __shared__ unsigned long long wd[HDIM][4][4];     // dup'd weight pairs, 32KB
    __shared__ unsigned long long part[2][4][32][4];  // [chain][wb][lane][g] partials, 8KB

    const int cta = blockIdx.x;
    const int dir = cta >> 6;
    const int cl  = cta & 63;
    const int u0  = cl * 4;
    const int t   = threadIdx.x;
    const int w   = t >> 5;
    const int l   = t & 31;
    const int ch  = w >> 3;             // chain 0/1
    const int wc  = w & 7;              // warp within chain
    const int ks  = wc >> 2;            // k slice 0/1
    const int wb  = wc & 3;             // batch group in chain
    const int ul  = l >> 3;             // unit 0..3
    const int bp  = l & 7;              // batch pair
    const int u   = u0 + ul;
    const int b0  = ch * 64 + wb * 16 + 2 * bp;
    const int kbase = ks * 128;
    const int barid = ch + 1;

    // stage dup'd weights (shared by both chains)
    for (int e = t; e < 256 * 16; e += 512) {
        int k = e >> 4, ui = (e >> 2) & 3, g = e & 3;
        float wv = g_Wt4[dir][k][u0 + ui][g];
        wd[k][ui][g] = pk2(wv, wv);
    }
    float c0 = 0.f, c1 = 0.f, h0v = 0.f, h1v = 0.f;
    if (ks == 0) {
        *(float2*)&g_h[dir][0][u][b0] = make_float2(0.f, 0.f);
        __threadfence();
    }
    __syncthreads();

    // initial dataflow barrier: publish 1, wait for all 64 producers >= 1
    if (wc == 0) {
        if (l == 0) g_prog[dir][ch][cl][0] = 1;
        bool ok;
        do {
            int v0 = g_prog[dir][ch][l][0];
            int v1 = g_prog[dir][ch][l + 32][0];
            ok = (v0 >= 1) && (v1 >= 1);
        } while (!__all_sync(0xffffffffu, ok));
        __threadfence();
    }
    named_bar(barid);

    const float* gxd = g_gx[dir];
    float2 gxq[4];
    if (ks == 0) {
#pragma unroll
        for (int g = 0; g < 4; g++)
            gxq[g] = __ldcg((const float2*)(gxd + ((size_t)0 * 1024 + g * 256 + u) * 128 + b0));
    }

    for (int s = 0; s < S_LEN; s++) {
        const int buf = s & 1;
        const float* hb = &g_h[dir][buf][0][0] + kbase * 128 + b0;

        unsigned long long acc[4] = {0ULL, 0ULL, 0ULL, 0ULL};
        unsigned long long hpA[8], hpB[8];
#pragma unroll
        for (int i = 0; i < 8; i++) hpA[i] = __ldcg((const unsigned long long*)(hb + i * 128));
#pragma unroll
        for (int i = 0; i < 8; i++) hpB[i] = __ldcg((const unsigned long long*)(hb + (8 + i) * 128));

        for (int kc = 0; kc < 16; kc += 2) {
            const int kA = kbase + kc * 8, kB = kA + 8;
#pragma unroll
            for (int i = 0; i < 8; i++) {
                ulonglong2 wif = *(const ulonglong2*)&wd[kA + i][ul][0];
                ulonglong2 wgo = *(const ulonglong2*)&wd[kA + i][ul][2];
                fma2(acc[0], wif.x, hpA[i]); fma2(acc[1], wif.y, hpA[i]);
                fma2(acc[2], wgo.x, hpA[i]); fma2(acc[3], wgo.y, hpA[i]);
            }
            if (kc + 2 < 16) {
                const float* src = hb + (kc + 2) * 8 * 128;
#pragma unroll
                for (int i = 0; i < 8; i++) hpA[i] = __ldcg((const unsigned long long*)(src + i * 128));
            }
#pragma unroll
            for (int i = 0; i < 8; i++) {
                ulonglong2 wif = *(const ulonglong2*)&wd[kB + i][ul][0];
                ulonglong2 wgo = *(const ulonglong2*)&wd[kB + i][ul][2];
                fma2(acc[0], wif.x, hpB[i]); fma2(acc[1], wif.y, hpB[i]);
                fma2(acc[2], wgo.x, hpB[i]); fma2(acc[3], wgo.y, hpB[i]);
            }
            if (kc + 3 < 16) {
                const float* src = hb + (kc + 3) * 8 * 128;
#pragma unroll
                for (int i = 0; i < 8; i++) hpB[i] = __ldcg((const unsigned long long*)(src + i * 128));
            }
        }
        if (ks == 1) {
            *(ulonglong2*)&part[ch][wb][l][0] = make_ulonglong2(acc[0], acc[1]);
            *(ulonglong2*)&part[ch][wb][l][2] = make_ulonglong2(acc[2], acc[3]);
        }
        named_bar(barid);
        if (ks == 0) {
            ulonglong2 p01 = *(const ulonglong2*)&part[ch][wb][l][0];
            ulonglong2 p23 = *(const ulonglong2*)&part[ch][wb][l][2];
            add2(acc[0], p01.x); add2(acc[1], p01.y);
            add2(acc[2], p23.x); add2(acc[3], p23.y);
            float2 vi = upk2(acc[0]), vf = upk2(acc[1]), vg = upk2(acc[2]), vo = upk2(acc[3]);
            {
                float gi = gxq[0].x + vi.x, gf = gxq[1].x + vf.x;
                float gg = gxq[2].x + vg.x, go = gxq[3].x + vo.x;
                float cc = sigmoidf_(gf) * c0 + sigmoidf_(gi) * tanhf_(gg);
                c0 = cc; h0v = sigmoidf_(go) * tanhf_(cc);
            }
            {
                float gi = gxq[0].y + vi.y, gf = gxq[1].y + vf.y;
                float gg = gxq[2].y + vg.y, go = gxq[3].y + vo.y;
                float cc = sigmoidf_(gf) * c1 + sigmoidf_(gi) * tanhf_(gg);
                c1 = cc; h1v = sigmoidf_(go) * tanhf_(cc);
            }
            __stcg((float2*)&g_h[dir][buf ^ 1][u][b0], make_float2(h0v, h1v));
            if (s + 1 < S_LEN) {
#pragma unroll
                for (int g = 0; g < 4; g++)
                    gxq[g] = __ldcg((const float2*)(gxd + ((size_t)(s + 1) * 1024 + g * 256 + u) * 128 + b0));
            }
            __threadfence();
        }
        named_bar(barid);
        // dataflow barrier: publish own progress, poll all 64 producers
        if (wc == 0) {
            const int tgt = s + 2;
            if (l == 0) g_prog[dir][ch][cl][0] = tgt;
            bool ok;
            do {
                int v0 = g_prog[dir][ch][l][0];
                int v1 = g_prog[dir][ch][l + 32][0];
                ok = (v0 >= tgt) && (v1 >= tgt);
            } while (!__all_sync(0xffffffffu, ok));
            __threadfence();
        }
        named_bar(barid);
    }
    if (ks == 0) {
        g_h0[(size_t)b0 * (2 * HDIM) + dir * HDIM + u]       = h0v;
        g_h0[(size_t)(b0 + 1) * (2 * HDIM) + dir * HDIM + u] = h1v;
    }
}

// ---------------- kernel 4: decoder input gates ------------------------------
__global__ __launch_bounds__(256) void dec_prep_kernel(
    const int* __restrict__ classes, const float* __restrict__ ecW,
    const float* __restrict__ dWih, const float* __restrict__ dbih)
{
    __shared__ float ce[EDIM];
    const int c = blockIdx.x;
    const int cls = classes[c];
    for (int e = threadIdx.x; e < EDIM; e += blockDim.x)
        ce[e] = tanhf_(ecW[(size_t)cls * EDIM + e]);
    __syncthreads();
    const int j = blockIdx.y * 256 + threadIdx.x;
    float acc = dbih[j];
    const float4* w = (const float4*)(dWih + (size_t)j * EDIM);
#pragma unroll 5
    for (int k = 0; k < EDIM / 4; k++) {
        float4 wv = w[k];
        acc += wv.x * ce[4 * k] + wv.y * ce[4 * k + 1] + wv.z * ce[4 * k + 2] + wv.w * ce[4 * k + 3];
    }
    g_gxc[c * 1536 + j] = acc;
}

// ---------------- kernel 5: decoder GRU + proj + cls + log_softmax ----------
__global__ __launch_bounds__(512) void dec_kernel(
    const float* __restrict__ dbhh,
    const float* __restrict__ projW, const float* __restrict__ projB,
    const float* __restrict__ clsW, const float* __restrict__ clsB,
    float* __restrict__ out)
{
    const int Gd = 2;
    const int H2 = 2 * HDIM;
    const int b0 = blockIdx.x * Gd;
    const int u  = threadIdx.x;
    const ulonglong2* W2 = (const ulonglong2*)&g_dWt4[0][0][0];

    __shared__ unsigned long long hd[2][Gd][512];
    __shared__ float hplain[Gd][512];
    __shared__ float projs[Gd][PDIM];
    __shared__ float lgs[Gd][2];

    float hprev[Gd];
#pragma unroll
    for (int b = 0; b < Gd; b++) {
        hprev[b] = g_h0[(size_t)(b0 + b) * H2 + u];
        hd[0][b][u] = pk2(hprev[b], hprev[b]);
    }
    const float bhr = dbhh[u], bhz = dbhh[H2 + u], bhn = dbhh[2 * H2 + u];
    __syncthreads();

    for (int c = 0; c < NCLS; c++) {
        const int cur = c & 1, nxt = cur ^ 1;
        unsigned long long arz[Gd], anp[Gd];
#pragma unroll
        for (int b = 0; b < Gd; b++) { arz[b] = 0ULL; anp[b] = 0ULL; }
        const unsigned long long* h0p = &hd[cur][0][0];
        const unsigned long long* h1p = &hd[cur][1][0];

#pragma unroll 4
        for (int k = 0; k < H2; k++) {
            ulonglong2 wv = W2[k * H2 + u];
            unsigned long long hh0 = h0p[k], hh1 = h1p[k];
            fma2(arz[0], wv.x, hh0); fma2(anp[0], wv.y, hh0);
            fma2(arz[1], wv.x, hh1); fma2(anp[1], wv.y, hh1);
        }
        const float gxr = g_gxc[c * 1536 + u];
        const float gxz = g_gxc[c * 1536 + H2 + u];
        const float gxn = g_gxc[c * 1536 + 2 * H2 + u];
#pragma unroll
        for (int b = 0; b < Gd; b++) {
            float2 vrz = upk2(arz[b]);
            float2 vnp = upk2(anp[b]);
            float r = sigmoidf_(gxr + vrz.x + bhr);
            float z = sigmoidf_(gxz + vrz.y + bhz);
            float n = tanhf_(gxn + r * (vnp.x + bhn));
            float hn = tanhf_((1.0f - z) * n + z * hprev[b]);
            hprev[b] = hn;
            hd[nxt][b][u] = pk2(hn, hn);
            hplain[b][u] = hn;
        }
        __syncthreads();
        {
            const int b = u >> 8, p = u & 255;
            const float4* wv = (const float4*)(projW + (size_t)p * H2);
            const float4* hv = (const float4*)hplain[b];
            float acc = projB[p];
            for (int k4 = 0; k4 < H2 / 4; k4++) {
                float4 w4 = wv[k4], h4 = hv[k4];
                acc += w4.x * h4.x + w4.y * h4.y + w4.z * h4.z + w4.w * h4.w;
            }
            projs[b][p] = acc;
        }
        __syncthreads();
        const int wid = u >> 5, lid = u & 31;
        if (wid < Gd * 2) {
            const int b = wid >> 1, cl = wid & 1;
            float acc = 0.0f;
            for (int k = lid; k < PDIM; k += 32) acc += clsW[cl * PDIM + k] * projs[b][k];
#pragma unroll
            for (int o = 16; o > 0; o >>= 1) acc += __shfl_down_sync(0xffffffffu, acc, o);
            if (lid == 0) lgs[b][cl] = acc + clsB[cl];
        }
        __syncthreads();
        if (u < Gd) {
            const int b = u;
            float l0 = lgs[b][0], l1 = lgs[b][1];
            float m = fmaxf(l0, l1);
            float lse = m + logf(expf(l0 - m) + expf(l1 - m));
            out[(size_t)c * BSZ * 2 + (b0 + b) * 2 + 0] = l0 - lse;
            out[(size_t)c * BSZ * 2 + (b0 + b) * 2 + 1] = l1 - lse;
        }
        __syncthreads();
    }
}

// ---------------- launch -----------------------------------------------------
extern "C" void kernel_launch(void* const* d_in, const int* in_sizes, int n_in,
                              void* d_out, int out_size)
{
    const int*   seq     = (const int*)d_in[0];
    const int*   classes = (const int*)d_in[1];
    const float* embW    = (const float*)d_in[2];
    const float* ecW     = (const float*)d_in[3];
    const float* fWih    = (const float*)d_in[4];
    const float* fWhh    = (const float*)d_in[5];
    const float* fbih    = (const float*)d_in[6];
    const float* fbhh    = (const float*)d_in[7];
    const float* bWih    = (const float*)d_in[8];
    const float* bWhh    = (const float*)d_in[9];
    const float* bbih    = (const float*)d_in[10];
    const float* bbhh    = (const float*)d_in[11];
    const float* dWih    = (const float*)d_in[12];
    const float* dWhh    = (const float*)d_in[13];
    const float* dbih    = (const float*)d_in[14];
    const float* dbhh    = (const float*)d_in[15];
    const float* projW   = (const float*)d_in[16];
    const float* projB   = (const float*)d_in[17];
    const float* clsW    = (const float*)d_in[18];
    const float* clsB    = (const float*)d_in[19];
    float* out = (float*)d_out;

    {   // 0. weight transposes + progress reset
        dim3 gl(HDIM / 32, HDIM / 32, 8);
        transpose_lstm_w<<<gl, 1024>>>(fWhh, bWhh);
        dim3 gd(2 * HDIM / 32, 2 * HDIM / 32, 3);
        transpose_dec_w<<<gd, 1024>>>(dWhh);
    }
    {   // 1. embeddings
        long long total = (long long)S_LEN * BSZ * EDIM;
        int blocks = (int)((total + 255) / 256);
        embed_kernel<<<blocks, 256>>>(seq, embW);
    }
    {   // 2. input-gate GEMMs, double-buffered
        dim3 grid(S_LEN, 1024 / 128, 2);
        gx_gemm_kernel<<<grid, 256>>>(fWih, fbih, fbhh, bWih, bbih, bbhh);
    }
    {   // 3. persistent bidirectional LSTM, two chains, dataflow sync
        lstm_persist<<<NCTA_LSTM, 512>>>();
    }
    {   // 4. decoder input gates per class
        dim3 grid(NCLS, 6);
        dec_prep_kernel<<<grid, 256>>>(classes, ecW, dWih, dbih);
    }
    {   // 5. decoder GRU + projection + classifier + log_softmax
        dec_kernel<<<BSZ / 2, 512>>>(dbhh, projW, projB, clsW, clsB, out);
    }
    (void)in_sizes; (void)n_in; (void)out_size;
}

// round 13
// speedup vs baseline: 1.6138x; 1.0974x over previous
#include <cuda_runtime.h>
#include <cuda_bf16.h>
#include <math.h>
#include <stdint.h>

#define S_LEN 512
#define BSZ   128
#define EDIM  300
#define HDIM  256
#define NCLS  6
#define PDIM  256
#define NCTA_LSTM 128            // 64 u-slice CTAs per direction

// ---------------- scratch (device globals; no runtime allocation) ----------
__device__ float g_seq_emb[(size_t)S_LEN * BSZ * EDIM];              // 78.6 MB
__device__ float g_gx[2][(size_t)S_LEN * 4 * HDIM * BSZ];            // [dir][s][col][b] 536 MB
__device__ float g_h[2][2][HDIM][BSZ];                               // [dir][buf][u][b]
__device__ float g_h0[(size_t)BSZ * 2 * HDIM];                       // concat [fh, bh]
__device__ float g_gxc[NCLS * 3 * 2 * HDIM];                         // decoder input gates
__device__ float g_Wt4[2][HDIM][HDIM][4];                            // [dir][k][u][gate i,f,g,o]
__device__ float g_dWt4[2 * HDIM][2 * HDIM][4];                      // [k][u][gate r,z,n,pad]
// per-CTA progress counters: [dir][chain][cta][pad to 128B] — NO shared atomics
__device__ volatile int g_prog[2][2][64][32];

// ---------------- helpers ---------------------------------------------------
__device__ __forceinline__ float sigmoidf_(float x) { return 1.0f / (1.0f + expf(-x)); }
__device__ __forceinline__ float tanhf_(float x) { return 1.0f - 2.0f / (expf(2.0f * x) + 1.0f); }

__device__ __forceinline__ unsigned long long pk2(float lo, float hi) {
    return ((unsigned long long)__float_as_uint(hi) << 32) | (unsigned long long)__float_as_uint(lo);
}
__device__ __forceinline__ float2 upk2(unsigned long long u) {
    float2 f; f.x = __uint_as_float((unsigned)u); f.y = __uint_as_float((unsigned)(u >> 32)); return f;
}
__device__ __forceinline__ void fma2(unsigned long long& d, unsigned long long a, unsigned long long b) {
    asm("fma.rn.f32x2 %0, %1, %2, %0;" : "+l"(d) : "l"(a), "l"(b));
}
__device__ __forceinline__ void add2(unsigned long long& d, unsigned long long a) {
    asm("add.rn.f32x2 %0, %0, %1;" : "+l"(d) : "l"(a));
}
__device__ __forceinline__ void named_bar(int id) {
    asm volatile("bar.sync %0, 256;" :: "r"(id) : "memory");
}
__device__ __forceinline__ uint32_t f2tf32(float x) {
    uint32_t r; asm("cvt.rna.tf32.f32 %0, %1;" : "=r"(r) : "f"(x)); return r;
}
__device__ __forceinline__ void mma_tf32(float c[4], uint32_t a0, uint32_t a1, uint32_t a2, uint32_t a3,
                                         uint32_t b0, uint32_t b1) {
    asm("mma.sync.aligned.m16n8k8.row.col.f32.tf32.tf32.f32 "
        "{%0,%1,%2,%3}, {%4,%5,%6,%7}, {%8,%9}, {%0,%1,%2,%3};"
        : "+f"(c[0]), "+f"(c[1]), "+f"(c[2]), "+f"(c[3])
        : "r"(a0), "r"(a1), "r"(a2), "r"(a3), "r"(b0), "r"(b1));
}

// ---------------- kernel 0a: transpose LSTM Whh + reset progress ------------
__global__ __launch_bounds__(1024) void transpose_lstm_w(const float* __restrict__ fWhh,
                                                         const float* __restrict__ bWhh)
{
    if (blockIdx.x == 0 && blockIdx.y == 0 && blockIdx.z == 0) {
        for (int i = threadIdx.x; i < 2 * 2 * 64 * 32; i += 1024) ((int*)g_prog)[i] = 0;
    }
    __shared__ float t[32][33];
    const int dir = blockIdx.z >> 2;
    const int g   = blockIdx.z & 3;
    const int k0  = blockIdx.x * 32;
    const int u0  = blockIdx.y * 32;
    const int tx = threadIdx.x & 31, ty = threadIdx.x >> 5;
    const float* W = dir ? bWhh : fWhh;
    t[ty][tx] = W[(size_t)(g * HDIM + u0 + ty) * HDIM + k0 + tx];
    __syncthreads();
    g_Wt4[dir][k0 + ty][u0 + tx][g] = t[tx][ty];
}

// ---------------- kernel 0b: transpose decoder Whh ---------------------------
__global__ __launch_bounds__(1024) void transpose_dec_w(const float* __restrict__ dWhh)
{
    __shared__ float t[32][33];
    const int g  = blockIdx.z;
    const int k0 = blockIdx.x * 32;
    const int u0 = blockIdx.y * 32;
    const int tx = threadIdx.x & 31, ty = threadIdx.x >> 5;
    t[ty][tx] = dWhh[(size_t)(g * 2 * HDIM + u0 + ty) * (2 * HDIM) + k0 + tx];
    __syncthreads();
    g_dWt4[k0 + ty][u0 + tx][g] = t[tx][ty];
}

// ---------------- kernel 1: embedding gather + tanh, time-major -------------
__global__ void embed_kernel(const int* __restrict__ seq, const float* __restrict__ embW) {
    long long idx = (long long)blockIdx.x * blockDim.x + threadIdx.x;
    const long long total = (long long)S_LEN * BSZ * EDIM;
    if (idx >= total) return;
    int e = (int)(idx % EDIM);
    int r = (int)(idx / EDIM);
    int b = r % BSZ;
    int s = r / BSZ;
    int v = seq[b * S_LEN + s];
    g_seq_emb[idx] = tanhf_(embW[(long long)v * EDIM + e]);
}

// ---------------- kernel 2: input GEMMs via tf32 tensor cores ---------------
// C[col][b] = sum_k W[col][k]*emb[b][k] + bias[col].  mma.m16n8k8.tf32:
// M=cols (W row-major = A operand), N=batch (emb k-contiguous = B col-major).
// 256 thr = 8 warps; warp = 16 cols x 128 batch = 16 MMAs per 8-k chunk.
// Smem k-major, stride 136 => fragment reads conflict-free (bank = 8k+col).
__global__ __launch_bounds__(256) void gx_gemm_tc(
    const float* __restrict__ fWih, const float* __restrict__ fbih, const float* __restrict__ fbhh,
    const float* __restrict__ bWih, const float* __restrict__ bbih, const float* __restrict__ bbhh)
{
    __shared__ uint32_t Ws[2][8][136];
    __shared__ uint32_t Es[2][8][136];

    const int dir   = blockIdx.z;
    const int s     = blockIdx.x;
    const int ntile = blockIdx.y;
    const float* W  = dir ? bWih : fWih;
    const float* bi = dir ? bbih : fbih;
    const float* bh = dir ? bbhh : fbhh;
    const int src_s = dir ? ((S_LEN - s) & (S_LEN - 1)) : s;
    const float* Abase = g_seq_emb + (size_t)src_s * BSZ * EDIM;

    const int t    = threadIdx.x;
    const int lane = t & 31;
    const int warp = t >> 5;
    const int c0w  = warp * 16;          // warp col base (within 128)
    const int grp  = lane >> 2;          // 0..7
    const int tig  = lane & 3;           // 0..3

    // bias-initialized accumulators (16 n-tiles x 4 regs)
    const int colg0 = ntile * 128 + c0w + grp;
    const int colg1 = colg0 + 8;
    const float bias0 = bi[colg0] + bh[colg0];
    const float bias1 = bi[colg1] + bh[colg1];
    float c[16][4];
#pragma unroll
    for (int nt = 0; nt < 16; nt++) {
        c[nt][0] = bias0; c[nt][1] = bias0;
        c[nt][2] = bias1; c[nt][3] = bias1;
    }

    // staging: thread -> (row = t>>1, k-quad = (t&1)*4); EDIM%4==0 -> quad all-or-none
    const int srow = t >> 1;
    const int skq  = (t & 1) * 4;
    const int NK   = (EDIM + 7) / 8;     // 38

    float4 wv = make_float4(0.f, 0.f, 0.f, 0.f);
    float4 ev = make_float4(0.f, 0.f, 0.f, 0.f);
    {
        const int kk = skq;
        if (kk + 3 < EDIM) {
            wv = *(const float4*)(W + (size_t)(ntile * 128 + srow) * EDIM + kk);
            ev = *(const float4*)(Abase + (size_t)srow * EDIM + kk);
        }
    }
    Ws[0][skq + 0][srow] = f2tf32(wv.x); Ws[0][skq + 1][srow] = f2tf32(wv.y);
    Ws[0][skq + 2][srow] = f2tf32(wv.z); Ws[0][skq + 3][srow] = f2tf32(wv.w);
    Es[0][skq + 0][srow] = f2tf32(ev.x); Es[0][skq + 1][srow] = f2tf32(ev.y);
    Es[0][skq + 2][srow] = f2tf32(ev.z); Es[0][skq + 3][srow] = f2tf32(ev.w);

    for (int kt = 0; kt < NK; kt++) {
        __syncthreads();
        const int cur = kt & 1;
        const bool more = (kt + 1 < NK);
        if (more) {
            const int kk = (kt + 1) * 8 + skq;
            wv = make_float4(0.f, 0.f, 0.f, 0.f);
            ev = make_float4(0.f, 0.f, 0.f, 0.f);
            if (kk + 3 < EDIM) {
                wv = *(const float4*)(W + (size_t)(ntile * 128 + srow) * EDIM + kk);
                ev = *(const float4*)(Abase + (size_t)srow * EDIM + kk);
            }
        }
        // A fragment (W): row=col, k
        uint32_t a0 = Ws[cur][tig][c0w + grp];
        uint32_t a1 = Ws[cur][tig][c0w + 8 + grp];
        uint32_t a2 = Ws[cur][tig + 4][c0w + grp];
        uint32_t a3 = Ws[cur][tig + 4][c0w + 8 + grp];
#pragma unroll
        for (int nt = 0; nt < 16; nt++) {
            uint32_t b0 = Es[cur][tig][nt * 8 + grp];
            uint32_t b1 = Es[cur][tig + 4][nt * 8 + grp];
            mma_tf32(c[nt], a0, a1, a2, a3, b0, b1);
        }
        if (more) {
            const int nxt = cur ^ 1;
            Ws[nxt][skq + 0][srow] = f2tf32(wv.x); Ws[nxt][skq + 1][srow] = f2tf32(wv.y);
            Ws[nxt][skq + 2][srow] = f2tf32(wv.z); Ws[nxt][skq + 3][srow] = f2tf32(wv.w);
            Es[nxt][skq + 0][srow] = f2tf32(ev.x); Es[nxt][skq + 1][srow] = f2tf32(ev.y);
            Es[nxt][skq + 2][srow] = f2tf32(ev.z); Es[nxt][skq + 3][srow] = f2tf32(ev.w);
        }
    }
    // epilogue: D(row=col, col=batch) -> g_gx[dir][s][col][b], float2 stores
    float* gbase = g_gx[dir] + (size_t)s * 1024 * 128;
#pragma unroll
    for (int nt = 0; nt < 16; nt++) {
        const int b = nt * 8 + 2 * tig;
        *(float2*)(gbase + (size_t)colg0 * 128 + b) = make_float2(c[nt][0], c[nt][1]);
        *(float2*)(gbase + (size_t)colg1 * 128 + b) = make_float2(c[nt][2], c[nt][3]);
    }
}

// ---------------- kernel 3: persistent LSTM, two chains, dataflow sync ------
// (unchanged from round 12 — the current best)
__global__ __launch_bounds__(512) void lstm_persist()
{
    __shared__ unsigned long long wd[HDIM][4][4];     // dup'd weight pairs, 32KB
    __shared__ unsigned long long part[2][4][32][4];  // [chain][wb][lane][g] partials, 8KB

    const int cta = blockIdx.x;
    const int dir = cta >> 6;
    const int cl  = cta & 63;
    const int u0  = cl * 4;
    const int t   = threadIdx.x;
    const int w   = t >> 5;
    const int l   = t & 31;
    const int ch  = w >> 3;
    const int wc  = w & 7;
    const int ks  = wc >> 2;
    const int wb  = wc & 3;
    const int ul  = l >> 3;
    const int bp  = l & 7;
    const int u   = u0 + ul;
    const int b0  = ch * 64 + wb * 16 + 2 * bp;
    const int kbase = ks * 128;
    const int barid = ch + 1;

    for (int e = t; e < 256 * 16; e += 512) {
        int k = e >> 4, ui = (e >> 2) & 3, g = e & 3;
        float wv = g_Wt4[dir][k][u0 + ui][g];
        wd[k][ui][g] = pk2(wv, wv);
    }
    float c0 = 0.f, c1 = 0.f, h0v = 0.f, h1v = 0.f;
    if (ks == 0) {
        *(float2*)&g_h[dir][0][u][b0] = make_float2(0.f, 0.f);
        __threadfence();
    }
    __syncthreads();

    if (wc == 0) {
        if (l == 0) g_prog[dir][ch][cl][0] = 1;
        bool ok;
        do {
            int v0 = g_prog[dir][ch][l][0];
            int v1 = g_prog[dir][ch][l + 32][0];
            ok = (v0 >= 1) && (v1 >= 1);
        } while (!__all_sync(0xffffffffu, ok));
        __threadfence();
    }
    named_bar(barid);

    const float* gxd = g_gx[dir];
    float2 gxq[4];
    if (ks == 0) {
#pragma unroll
        for (int g = 0; g < 4; g++)
            gxq[g] = __ldcg((const float2*)(gxd + ((size_t)0 * 1024 + g * 256 + u) * 128 + b0));
    }

    for (int s = 0; s < S_LEN; s++) {
        const int buf = s & 1;
        const float* hb = &g_h[dir][buf][0][0] + kbase * 128 + b0;

        unsigned long long acc[4] = {0ULL, 0ULL, 0ULL, 0ULL};
        unsigned long long hpA[8], hpB[8];
#pragma unroll
        for (int i = 0; i < 8; i++) hpA[i] = __ldcg((const unsigned long long*)(hb + i * 128));
#pragma unroll
        for (int i = 0; i < 8; i++) hpB[i] = __ldcg((const unsigned long long*)(hb + (8 + i) * 128));

        for (int kc = 0; kc < 16; kc += 2) {
            const int kA = kbase + kc * 8, kB = kA + 8;
#pragma unroll
            for (int i = 0; i < 8; i++) {
                ulonglong2 wif = *(const ulonglong2*)&wd[kA + i][ul][0];
                ulonglong2 wgo = *(const ulonglong2*)&wd[kA + i][ul][2];
                fma2(acc[0], wif.x, hpA[i]); fma2(acc[1], wif.y, hpA[i]);
                fma2(acc[2], wgo.x, hpA[i]); fma2(acc[3], wgo.y, hpA[i]);
            }
            if (kc + 2 < 16) {
                const float* src = hb + (kc + 2) * 8 * 128;
#pragma unroll
                for (int i = 0; i < 8; i++) hpA[i] = __ldcg((const unsigned long long*)(src + i * 128));
            }
#pragma unroll
            for (int i = 0; i < 8; i++) {
                ulonglong2 wif = *(const ulonglong2*)&wd[kB + i][ul][0];
                ulonglong2 wgo = *(const ulonglong2*)&wd[kB + i][ul][2];
                fma2(acc[0], wif.x, hpB[i]); fma2(acc[1], wif.y, hpB[i]);
                fma2(acc[2], wgo.x, hpB[i]); fma2(acc[3], wgo.y, hpB[i]);
            }
            if (kc + 3 < 16) {
                const float* src = hb + (kc + 3) * 8 * 128;
#pragma unroll
                for (int i = 0; i < 8; i++) hpB[i] = __ldcg((const unsigned long long*)(src + i * 128));
            }
        }
        if (ks == 1) {
            *(ulonglong2*)&part[ch][wb][l][0] = make_ulonglong2(acc[0], acc[1]);
            *(ulonglong2*)&part[ch][wb][l][2] = make_ulonglong2(acc[2], acc[3]);
        }
        named_bar(barid);
        if (ks == 0) {
            ulonglong2 p01 = *(const ulonglong2*)&part[ch][wb][l][0];
            ulonglong2 p23 = *(const ulonglong2*)&part[ch][wb][l][2];
            add2(acc[0], p01.x); add2(acc[1], p01.y);
            add2(acc[2], p23.x); add2(acc[3], p23.y);
            float2 vi = upk2(acc[0]), vf = upk2(acc[1]), vg = upk2(acc[2]), vo = upk2(acc[3]);
            {
                float gi = gxq[0].x + vi.x, gf = gxq[1].x + vf.x;
                float gg = gxq[2].x + vg.x, go = gxq[3].x + vo.x;
                float cc = sigmoidf_(gf) * c0 + sigmoidf_(gi) * tanhf_(gg);
                c0 = cc; h0v = sigmoidf_(go) * tanhf_(cc);
            }
            {
                float gi = gxq[0].y + vi.y, gf = gxq[1].y + vf.y;
                float gg = gxq[2].y + vg.y, go = gxq[3].y + vo.y;
                float cc = sigmoidf_(gf) * c1 + sigmoidf_(gi) * tanhf_(gg);
                c1 = cc; h1v = sigmoidf_(go) * tanhf_(cc);
            }
            __stcg((float2*)&g_h[dir][buf ^ 1][u][b0], make_float2(h0v, h1v));
            if (s + 1 < S_LEN) {
#pragma unroll
                for (int g = 0; g < 4; g++)
                    gxq[g] = __ldcg((const float2*)(gxd + ((size_t)(s + 1) * 1024 + g * 256 + u) * 128 + b0));
            }
            __threadfence();
        }
        named_bar(barid);
        if (wc == 0) {
            const int tgt = s + 2;
            if (l == 0) g_prog[dir][ch][cl][0] = tgt;
            bool ok;
            do {
                int v0 = g_prog[dir][ch][l][0];
                int v1 = g_prog[dir][ch][l + 32][0];
                ok = (v0 >= tgt) && (v1 >= tgt);
            } while (!__all_sync(0xffffffffu, ok));
            __threadfence();
        }
        named_bar(barid);
    }
    if (ks == 0) {
        g_h0[(size_t)b0 * (2 * HDIM) + dir * HDIM + u]       = h0v;
        g_h0[(size_t)(b0 + 1) * (2 * HDIM) + dir * HDIM + u] = h1v;
    }
}

// ---------------- kernel 4: decoder input gates ------------------------------
__global__ __launch_bounds__(256) void dec_prep_kernel(
    const int* __restrict__ classes, const float* __restrict__ ecW,
    const float* __restrict__ dWih, const float* __restrict__ dbih)
{
    __shared__ float ce[EDIM];
    const int c = blockIdx.x;
    const int cls = classes[c];
    for (int e = threadIdx.x; e < EDIM; e += blockDim.x)
        ce[e] = tanhf_(ecW[(size_t)cls * EDIM + e]);
    __syncthreads();
    const int j = blockIdx.y * 256 + threadIdx.x;
    float acc = dbih[j];
    const float4* w = (const float4*)(dWih + (size_t)j * EDIM);
#pragma unroll 5
    for (int k = 0; k < EDIM / 4; k++) {
        float4 wv = w[k];
        acc += wv.x * ce[4 * k] + wv.y * ce[4 * k + 1] + wv.z * ce[4 * k + 2] + wv.w * ce[4 * k + 3];
    }
    g_gxc[c * 1536 + j] = acc;
}

// ---------------- kernel 5: decoder GRU + proj + cls + log_softmax ----------
__global__ __launch_bounds__(512) void dec_kernel(
    const float* __restrict__ dbhh,
    const float* __restrict__ projW, const float* __restrict__ projB,
    const float* __restrict__ clsW, const float* __restrict__ clsB,
    float* __restrict__ out)
{
    const int Gd = 2;
    const int H2 = 2 * HDIM;
    const int b0 = blockIdx.x * Gd;
    const int u  = threadIdx.x;
    const ulonglong2* W2 = (const ulonglong2*)&g_dWt4[0][0][0];

    __shared__ unsigned long long hd[2][Gd][512];
    __shared__ float hplain[Gd][512];
    __shared__ float projs[Gd][PDIM];
    __shared__ float lgs[Gd][2];

    float hprev[Gd];
#pragma unroll
    for (int b = 0; b < Gd; b++) {
        hprev[b] = g_h0[(size_t)(b0 + b) * H2 + u];
        hd[0][b][u] = pk2(hprev[b], hprev[b]);
    }
    const float bhr = dbhh[u], bhz = dbhh[H2 + u], bhn = dbhh[2 * H2 + u];
    __syncthreads();

    for (int c = 0; c < NCLS; c++) {
        const int cur = c & 1, nxt = cur ^ 1;
        unsigned long long arz[Gd], anp[Gd];
#pragma unroll
        for (int b = 0; b < Gd; b++) { arz[b] = 0ULL; anp[b] = 0ULL; }
        const unsigned long long* h0p = &hd[cur][0][0];
        const unsigned long long* h1p = &hd[cur][1][0];

#pragma unroll 4
        for (int k = 0; k < H2; k++) {
            ulonglong2 wv = W2[k * H2 + u];
            unsigned long long hh0 = h0p[k], hh1 = h1p[k];
            fma2(arz[0], wv.x, hh0); fma2(anp[0], wv.y, hh0);
            fma2(arz[1], wv.x, hh1); fma2(anp[1], wv.y, hh1);
        }
        const float gxr = g_gxc[c * 1536 + u];
        const float gxz = g_gxc[c * 1536 + H2 + u];
        const float gxn = g_gxc[c * 1536 + 2 * H2 + u];
#pragma unroll
        for (int b = 0; b < Gd; b++) {
            float2 vrz = upk2(arz[b]);
            float2 vnp = upk2(anp[b]);
            float r = sigmoidf_(gxr + vrz.x + bhr);
            float z = sigmoidf_(gxz + vrz.y + bhz);
            float n = tanhf_(gxn + r * (vnp.x + bhn));
            float hn = tanhf_((1.0f - z) * n + z * hprev[b]);
            hprev[b] = hn;
            hd[nxt][b][u] = pk2(hn, hn);
            hplain[b][u] = hn;
        }
        __syncthreads();
        {
            const int b = u >> 8, p = u & 255;
            const float4* wv = (const float4*)(projW + (size_t)p * H2);
            const float4* hv = (const float4*)hplain[b];
            float acc = projB[p];
            for (int k4 = 0; k4 < H2 / 4; k4++) {
                float4 w4 = wv[k4], h4 = hv[k4];
                acc += w4.x * h4.x + w4.y * h4.y + w4.z * h4.z + w4.w * h4.w;
            }
            projs[b][p] = acc;
        }
        __syncthreads();
        const int wid = u >> 5, lid = u & 31;
        if (wid < Gd * 2) {
            const int b = wid >> 1, cl = wid & 1;
            float acc = 0.0f;
            for (int k = lid; k < PDIM; k += 32) acc += clsW[cl * PDIM + k] * projs[b][k];
#pragma unroll
            for (int o = 16; o > 0; o >>= 1) acc += __shfl_down_sync(0xffffffffu, acc, o);
            if (lid == 0) lgs[b][cl] = acc + clsB[cl];
        }
        __syncthreads();
        if (u < Gd) {
            const int b = u;
            float l0 = lgs[b][0], l1 = lgs[b][1];
            float m = fmaxf(l0, l1);
            float lse = m + logf(expf(l0 - m) + expf(l1 - m));
            out[(size_t)c * BSZ * 2 + (b0 + b) * 2 + 0] = l0 - lse;
            out[(size_t)c * BSZ * 2 + (b0 + b) * 2 + 1] = l1 - lse;
        }
        __syncthreads();
    }
}

// ---------------- launch -----------------------------------------------------
extern "C" void kernel_launch(void* const* d_in, const int* in_sizes, int n_in,
                              void* d_out, int out_size)
{
    const int*   seq     = (const int*)d_in[0];
    const int*   classes = (const int*)d_in[1];
    const float* embW    = (const float*)d_in[2];
    const float* ecW     = (const float*)d_in[3];
    const float* fWih    = (const float*)d_in[4];
    const float* fWhh    = (const float*)d_in[5];
    const float* fbih    = (const float*)d_in[6];
    const float* fbhh    = (const float*)d_in[7];
    const float* bWih    = (const float*)d_in[8];
    const float* bWhh    = (const float*)d_in[9];
    const float* bbih    = (const float*)d_in[10];
    const float* bbhh    = (const float*)d_in[11];
    const float* dWih    = (const float*)d_in[12];
    const float* dWhh    = (const float*)d_in[13];
    const float* dbih    = (const float*)d_in[14];
    const float* dbhh    = (const float*)d_in[15];
    const float* projW   = (const float*)d_in[16];
    const float* projB   = (const float*)d_in[17];
    const float* clsW    = (const float*)d_in[18];
    const float* clsB    = (const float*)d_in[19];
    float* out = (float*)d_out;

    {   // 0. weight transposes + progress reset
        dim3 gl(HDIM / 32, HDIM / 32, 8);
        transpose_lstm_w<<<gl, 1024>>>(fWhh, bWhh);
        dim3 gd(2 * HDIM / 32, 2 * HDIM / 32, 3);
        transpose_dec_w<<<gd, 1024>>>(dWhh);
    }
    {   // 1. embeddings
        long long total = (long long)S_LEN * BSZ * EDIM;
        int blocks = (int)((total + 255) / 256);
        embed_kernel<<<blocks, 256>>>(seq, embW);
    }
    {   // 2. input-gate GEMMs on tf32 tensor cores
        dim3 grid(S_LEN, 1024 / 128, 2);
        gx_gemm_tc<<<grid, 256>>>(fWih, fbih, fbhh, bWih, bbih, bbhh);
    }
    {   // 3. persistent bidirectional LSTM, two chains, dataflow sync
        lstm_persist<<<NCTA_LSTM, 512>>>();
    }
    {   // 4. decoder input gates per class
        dim3 grid(NCLS, 6);
        dec_prep_kernel<<<grid, 256>>>(classes, ecW, dWih, dbih);
    }
    {   // 5. decoder GRU + projection + classifier + log_softmax
        dec_kernel<<<BSZ / 2, 512>>>(dbhh, projW, projB, clsW, clsB, out);
    }
    (void)in_sizes; (void)n_in; (void)out_size;
}

// round 14
// speedup vs baseline: 1.6419x; 1.0174x over previous
#include <cuda_runtime.h>
#include <cuda_bf16.h>
#include <math.h>
#include <stdint.h>

#define S_LEN 512
#define BSZ   128
#define EDIM  300
#define HDIM  256
#define NCLS  6
#define PDIM  256
#define NCTA_LSTM 128            // 64 u-slice CTAs per direction
#define NKT8  38                 // number of 8-k tiles (304 padded)

// ---------------- scratch (device globals; no runtime allocation) ----------
__device__ float g_seq_emb[(size_t)S_LEN * BSZ * EDIM];              // tf32-rounded
__device__ float g_gx[2][(size_t)S_LEN * 4 * HDIM * BSZ];            // [dir][s][col][b] 536 MB
__device__ float g_h[2][2][HDIM][BSZ];                               // [dir][buf][u][b]
__device__ float g_h0[(size_t)BSZ * 2 * HDIM];                       // concat [fh, bh]
__device__ float g_gxc[NCLS * 3 * 2 * HDIM];                         // decoder input gates
__device__ float g_Wt4[2][HDIM][HDIM][4];                            // [dir][k][u][gate i,f,g,o]
__device__ float g_dWt4[2 * HDIM][2 * HDIM][4];                      // [k][u][gate r,z,n,pad]
__device__ float g_Wfrag[2][8][8][NKT8][32][4];                      // tf32 A-fragments, 6.2 MB
// per-CTA progress counters: [dir][chain][cta][pad to 128B] — NO shared atomics
__device__ volatile int g_prog[2][2][64][32];

// ---------------- helpers ---------------------------------------------------
__device__ __forceinline__ float sigmoidf_(float x) { return 1.0f / (1.0f + expf(-x)); }
__device__ __forceinline__ float tanhf_(float x) { return 1.0f - 2.0f / (expf(2.0f * x) + 1.0f); }

__device__ __forceinline__ unsigned long long pk2(float lo, float hi) {
    return ((unsigned long long)__float_as_uint(hi) << 32) | (unsigned long long)__float_as_uint(lo);
}
__device__ __forceinline__ float2 upk2(unsigned long long u) {
    float2 f; f.x = __uint_as_float((unsigned)u); f.y = __uint_as_float((unsigned)(u >> 32)); return f;
}
__device__ __forceinline__ void fma2(unsigned long long& d, unsigned long long a, unsigned long long b) {
    asm("fma.rn.f32x2 %0, %1, %2, %0;" : "+l"(d) : "l"(a), "l"(b));
}
__device__ __forceinline__ void add2(unsigned long long& d, unsigned long long a) {
    asm("add.rn.f32x2 %0, %0, %1;" : "+l"(d) : "l"(a));
}
__device__ __forceinline__ void named_bar(int id) {
    asm volatile("bar.sync %0, 256;" :: "r"(id) : "memory");
}
__device__ __forceinline__ uint32_t f2tf32(float x) {
    uint32_t r; asm("cvt.rna.tf32.f32 %0, %1;" : "=r"(r) : "f"(x)); return r;
}
__device__ __forceinline__ void mma_tf32(float c[4], uint32_t a0, uint32_t a1, uint32_t a2, uint32_t a3,
                                         uint32_t b0, uint32_t b1) {
    asm("mma.sync.aligned.m16n8k8.row.col.f32.tf32.tf32.f32 "
        "{%0,%1,%2,%3}, {%4,%5,%6,%7}, {%8,%9}, {%0,%1,%2,%3};"
        : "+f"(c[0]), "+f"(c[1]), "+f"(c[2]), "+f"(c[3])
        : "r"(a0), "r"(a1), "r"(a2), "r"(a3), "r"(b0), "r"(b1));
}

// ---------------- kernel 0a: transpose LSTM Whh + reset progress ------------
__global__ __launch_bounds__(1024) void transpose_lstm_w(const float* __restrict__ fWhh,
                                                         const float* __restrict__ bWhh)
{
    if (blockIdx.x == 0 && blockIdx.y == 0 && blockIdx.z == 0) {
        for (int i = threadIdx.x; i < 2 * 2 * 64 * 32; i += 1024) ((int*)g_prog)[i] = 0;
    }
    __shared__ float t[32][33];
    const int dir = blockIdx.z >> 2;
    const int g   = blockIdx.z & 3;
    const int k0  = blockIdx.x * 32;
    const int u0  = blockIdx.y * 32;
    const int tx = threadIdx.x & 31, ty = threadIdx.x >> 5;
    const float* W = dir ? bWhh : fWhh;
    t[ty][tx] = W[(size_t)(g * HDIM + u0 + ty) * HDIM + k0 + tx];
    __syncthreads();
    g_Wt4[dir][k0 + ty][u0 + tx][g] = t[tx][ty];
}

// ---------------- kernel 0b: transpose decoder Whh ---------------------------
__global__ __launch_bounds__(1024) void transpose_dec_w(const float* __restrict__ dWhh)
{
    __shared__ float t[32][33];
    const int g  = blockIdx.z;
    const int k0 = blockIdx.x * 32;
    const int u0 = blockIdx.y * 32;
    const int tx = threadIdx.x & 31, ty = threadIdx.x >> 5;
    t[ty][tx] = dWhh[(size_t)(g * 2 * HDIM + u0 + ty) * (2 * HDIM) + k0 + tx];
    __syncthreads();
    g_dWt4[k0 + ty][u0 + tx][g] = t[tx][ty];
}

// ---------------- kernel 0c: pack Wih into tf32 mma A-fragments --------------
// g_Wfrag[dir][ntile][warp][kt][lane] = {A(col0,k0), A(col1,k0), A(col0,k1), A(col1,k1)}
__global__ __launch_bounds__(256) void pack_wfrag(const float* __restrict__ fWih,
                                                  const float* __restrict__ bWih)
{
    const int idx = blockIdx.x * 256 + threadIdx.x;
    const int total = 2 * 8 * 8 * NKT8 * 32;
    if (idx >= total) return;
    const int lane  = idx & 31;
    const int kt    = (idx >> 5) % NKT8;
    const int warp  = ((idx >> 5) / NKT8) & 7;
    const int ntile = ((idx >> 5) / (NKT8 * 8)) & 7;
    const int dir   = idx / (32 * NKT8 * 8 * 8);
    const float* W = dir ? bWih : fWih;
    const int grp = lane >> 2, tig = lane & 3;
    const int col0 = ntile * 128 + warp * 16 + grp;
    const int col1 = col0 + 8;
    const int k0 = kt * 8 + tig, k1 = k0 + 4;
    float a0 = (k0 < EDIM) ? W[(size_t)col0 * EDIM + k0] : 0.f;
    float a1 = (k0 < EDIM) ? W[(size_t)col1 * EDIM + k0] : 0.f;
    float a2 = (k1 < EDIM) ? W[(size_t)col0 * EDIM + k1] : 0.f;
    float a3 = (k1 < EDIM) ? W[(size_t)col1 * EDIM + k1] : 0.f;
    float* dst = &g_Wfrag[dir][ntile][warp][kt][lane][0];
    dst[0] = __uint_as_float(f2tf32(a0));
    dst[1] = __uint_as_float(f2tf32(a1));
    dst[2] = __uint_as_float(f2tf32(a2));
    dst[3] = __uint_as_float(f2tf32(a3));
}

// ---------------- kernel 1: embedding gather + tanh + tf32 round ------------
__global__ void embed_kernel(const int* __restrict__ seq, const float* __restrict__ embW) {
    long long idx = (long long)blockIdx.x * blockDim.x + threadIdx.x;
    const long long total = (long long)S_LEN * BSZ * EDIM;
    if (idx >= total) return;
    int e = (int)(idx % EDIM);
    int r = (int)(idx / EDIM);
    int b = r % BSZ;
    int s = r / BSZ;
    int v = seq[b * S_LEN + s];
    g_seq_emb[idx] = __uint_as_float(f2tf32(tanhf_(embW[(long long)v * EDIM + e])));
}

// ---------------- kernel 2: input GEMMs via tf32 tensor cores (v2) ----------
// W as prepacked fragments (1 LDG.128/warp/8k, no smem); E staged k-major in
// smem (no cvt — pre-rounded), BK=16, double-buffered, 19 sync iterations.
__global__ __launch_bounds__(256) void gx_gemm_tc(
    const float* __restrict__ fbih, const float* __restrict__ fbhh,
    const float* __restrict__ bbih, const float* __restrict__ bbhh)
{
    __shared__ uint32_t Es[2][16][136];

    const int dir   = blockIdx.z;
    const int s     = blockIdx.x;
    const int ntile = blockIdx.y;
    const float* bi = dir ? bbih : fbih;
    const float* bh = dir ? bbhh : fbhh;
    const int src_s = dir ? ((S_LEN - s) & (S_LEN - 1)) : s;
    const float* Abase = g_seq_emb + (size_t)src_s * BSZ * EDIM;

    const int t    = threadIdx.x;
    const int lane = t & 31;
    const int warp = t >> 5;
    const int grp  = lane >> 2;          // 0..7
    const int tig  = lane & 3;           // 0..3

    const int colg0 = ntile * 128 + warp * 16 + grp;
    const int colg1 = colg0 + 8;
    const float bias0 = bi[colg0] + bh[colg0];
    const float bias1 = bi[colg1] + bh[colg1];
    float c[16][4];
#pragma unroll
    for (int nt = 0; nt < 16; nt++) {
        c[nt][0] = bias0; c[nt][1] = bias0;
        c[nt][2] = bias1; c[nt][3] = bias1;
    }

    // W fragment stream (fragment-major, stride 32 float4 per 8-k tile)
    const float4* wf = (const float4*)&g_Wfrag[dir][ntile][warp][0][lane][0];
    float4 af0 = wf[0];
    float4 af1 = wf[32];

    // E staging map: thread -> (row = t>>1, k-half = (t&1)*8)
    const int srow = t >> 1;
    const int kh   = (t & 1) * 8;
    const int NK2  = (NKT8 + 1) / 2;     // 19 BK=16 iterations

    float4 evA = make_float4(0.f, 0.f, 0.f, 0.f);
    float4 evB = make_float4(0.f, 0.f, 0.f, 0.f);
    {
        const int kk = kh;
        if (kk + 3 < EDIM)  evA = *(const float4*)(Abase + (size_t)srow * EDIM + kk);
        if (kk + 7 < EDIM)  evB = *(const float4*)(Abase + (size_t)srow * EDIM + kk + 4);
    }
    Es[0][kh + 0][srow] = __float_as_uint(evA.x); Es[0][kh + 1][srow] = __float_as_uint(evA.y);
    Es[0][kh + 2][srow] = __float_as_uint(evA.z); Es[0][kh + 3][srow] = __float_as_uint(evA.w);
    Es[0][kh + 4][srow] = __float_as_uint(evB.x); Es[0][kh + 5][srow] = __float_as_uint(evB.y);
    Es[0][kh + 6][srow] = __float_as_uint(evB.z); Es[0][kh + 7][srow] = __float_as_uint(evB.w);

    for (int kt2 = 0; kt2 < NK2; kt2++) {
        __syncthreads();
        const int cur = kt2 & 1;
        const bool more = (kt2 + 1 < NK2);
        if (more) {
            const int kk = (kt2 + 1) * 16 + kh;
            evA = make_float4(0.f, 0.f, 0.f, 0.f);
            evB = make_float4(0.f, 0.f, 0.f, 0.f);
            if (kk + 3 < EDIM) evA = *(const float4*)(Abase + (size_t)srow * EDIM + kk);
            if (kk + 7 < EDIM) evB = *(const float4*)(Abase + (size_t)srow * EDIM + kk + 4);
        }
        // half-tile 0 (k = kt2*16 .. +7)
        {
            uint32_t a0 = __float_as_uint(af0.x), a1 = __float_as_uint(af0.y);
            uint32_t a2 = __float_as_uint(af0.z), a3 = __float_as_uint(af0.w);
#pragma unroll
            for (int nt = 0; nt < 16; nt++) {
                uint32_t b0 = Es[cur][tig][nt * 8 + grp];
                uint32_t b1 = Es[cur][tig + 4][nt * 8 + grp];
                mma_tf32(c[nt], a0, a1, a2, a3, b0, b1);
            }
        }
        // half-tile 1 (k = kt2*16+8 .. +15)
        {
            uint32_t a0 = __float_as_uint(af1.x), a1 = __float_as_uint(af1.y);
            uint32_t a2 = __float_as_uint(af1.z), a3 = __float_as_uint(af1.w);
#pragma unroll
            for (int nt = 0; nt < 16; nt++) {
                uint32_t b0 = Es[cur][8 + tig][nt * 8 + grp];
                uint32_t b1 = Es[cur][8 + tig + 4][nt * 8 + grp];
                mma_tf32(c[nt], a0, a1, a2, a3, b0, b1);
            }
        }
        if (more) {
            af0 = wf[(2 * kt2 + 2) * 32];
            af1 = wf[(2 * kt2 + 3) * 32];
            const int nxt = cur ^ 1;
            Es[nxt][kh + 0][srow] = __float_as_uint(evA.x); Es[nxt][kh + 1][srow] = __float_as_uint(evA.y);
            Es[nxt][kh + 2][srow] = __float_as_uint(evA.z); Es[nxt][kh + 3][srow] = __float_as_uint(evA.w);
            Es[nxt][kh + 4][srow] = __float_as_uint(evB.x); Es[nxt][kh + 5][srow] = __float_as_uint(evB.y);
            Es[nxt][kh + 6][srow] = __float_as_uint(evB.z); Es[nxt][kh + 7][srow] = __float_as_uint(evB.w);
        }
    }
    // epilogue: D(row=col, col=batch) -> g_gx[dir][s][col][b], float2 stores
    float* gbase = g_gx[dir] + (size_t)s * 1024 * 128;
#pragma unroll
    for (int nt = 0; nt < 16; nt++) {
        const int b = nt * 8 + 2 * tig;
        *(float2*)(gbase + (size_t)colg0 * 128 + b) = make_float2(c[nt][0], c[nt][1]);
        *(float2*)(gbase + (size_t)colg1 * 128 + b) = make_float2(c[nt][2], c[nt][3]);
    }
}

// ---------------- kernel 3: persistent LSTM, two chains, dataflow sync ------
// (unchanged — current best)
__global__ __launch_bounds__(512) void lstm_persist()
{
    __shared__ unsigned long long wd[HDIM][4][4];     // dup'd weight pairs, 32KB
    __shared__ unsigned long long part[2][4][32][4];  // [chain][wb][lane][g] partials, 8KB

    const int cta = blockIdx.x;
    const int dir = cta >> 6;
    const int cl  = cta & 63;
    const int u0  = cl * 4;
    const int t   = threadIdx.x;
    const int w   = t >> 5;
    const int l   = t & 31;
    const int ch  = w >> 3;
    const int wc  = w & 7;
    const int ks  = wc >> 2;
    const int wb  = wc & 3;
    const int ul  = l >> 3;
    const int bp  = l & 7;
    const int u   = u0 + ul;
    const int b0  = ch * 64 + wb * 16 + 2 * bp;
    const int kbase = ks * 128;
    const int barid = ch + 1;

    for (int e = t; e < 256 * 16; e += 512) {
        int k = e >> 4, ui = (e >> 2) & 3, g = e & 3;
        float wv = g_Wt4[dir][k][u0 + ui][g];
        wd[k][ui][g] = pk2(wv, wv);
    }
    float c0 = 0.f, c1 = 0.f, h0v = 0.f, h1v = 0.f;
    if (ks == 0) {
        *(float2*)&g_h[dir][0][u][b0] = make_float2(0.f, 0.f);
        __threadfence();
    }
    __syncthreads();

    if (wc == 0) {
        if (l == 0) g_prog[dir][ch][cl][0] = 1;
        bool ok;
        do {
            int v0 = g_prog[dir][ch][l][0];
            int v1 = g_prog[dir][ch][l + 32][0];
            ok = (v0 >= 1) && (v1 >= 1);
        } while (!__all_sync(0xffffffffu, ok));
        __threadfence();
    }
    named_bar(barid);

    const float* gxd = g_gx[dir];
    float2 gxq[4];
    if (ks == 0) {
#pragma unroll
        for (int g = 0; g < 4; g++)
            gxq[g] = __ldcg((const float2*)(gxd + ((size_t)0 * 1024 + g * 256 + u) * 128 + b0));
    }

    for (int s = 0; s < S_LEN; s++) {
        const int buf = s & 1;
        const float* hb = &g_h[dir][buf][0][0] + kbase * 128 + b0;

        unsigned long long acc[4] = {0ULL, 0ULL, 0ULL, 0ULL};
        unsigned long long hpA[8], hpB[8];
#pragma unroll
        for (int i = 0; i < 8; i++) hpA[i] = __ldcg((const unsigned long long*)(hb + i * 128));
#pragma unroll
        for (int i = 0; i < 8; i++) hpB[i] = __ldcg((const unsigned long long*)(hb + (8 + i) * 128));

        for (int kc = 0; kc < 16; kc += 2) {
            const int kA = kbase + kc * 8, kB = kA + 8;
#pragma unroll
            for (int i = 0; i < 8; i++) {
                ulonglong2 wif = *(const ulonglong2*)&wd[kA + i][ul][0];
                ulonglong2 wgo = *(const ulonglong2*)&wd[kA + i][ul][2];
                fma2(acc[0], wif.x, hpA[i]); fma2(acc[1], wif.y, hpA[i]);
                fma2(acc[2], wgo.x, hpA[i]); fma2(acc[3], wgo.y, hpA[i]);
            }
            if (kc + 2 < 16) {
                const float* src = hb + (kc + 2) * 8 * 128;
#pragma unroll
                for (int i = 0; i < 8; i++) hpA[i] = __ldcg((const unsigned long long*)(src + i * 128));
            }
#pragma unroll
            for (int i = 0; i < 8; i++) {
                ulonglong2 wif = *(const ulonglong2*)&wd[kB + i][ul][0];
                ulonglong2 wgo = *(const ulonglong2*)&wd[kB + i][ul][2];
                fma2(acc[0], wif.x, hpB[i]); fma2(acc[1], wif.y, hpB[i]);
                fma2(acc[2], wgo.x, hpB[i]); fma2(acc[3], wgo.y, hpB[i]);
            }
            if (kc + 3 < 16) {
                const float* src = hb + (kc + 3) * 8 * 128;
#pragma unroll
                for (int i = 0; i < 8; i++) hpB[i] = __ldcg((const unsigned long long*)(src + i * 128));
            }
        }
        if (ks == 1) {
            *(ulonglong2*)&part[ch][wb][l][0] = make_ulonglong2(acc[0], acc[1]);
            *(ulonglong2*)&part[ch][wb][l][2] = make_ulonglong2(acc[2], acc[3]);
        }
        named_bar(barid);
        if (ks == 0) {
            ulonglong2 p01 = *(const ulonglong2*)&part[ch][wb][l][0];
            ulonglong2 p23 = *(const ulonglong2*)&part[ch][wb][l][2];
            add2(acc[0], p01.x); add2(acc[1], p01.y);
            add2(acc[2], p23.x); add2(acc[3], p23.y);
            float2 vi = upk2(acc[0]), vf = upk2(acc[1]), vg = upk2(acc[2]), vo = upk2(acc[3]);
            {
                float gi = gxq[0].x + vi.x, gf = gxq[1].x + vf.x;
                float gg = gxq[2].x + vg.x, go = gxq[3].x + vo.x;
                float cc = sigmoidf_(gf) * c0 + sigmoidf_(gi) * tanhf_(gg);
                c0 = cc; h0v = sigmoidf_(go) * tanhf_(cc);
            }
            {
                float gi = gxq[0].y + vi.y, gf = gxq[1].y + vf.y;
                float gg = gxq[2].y + vg.y, go = gxq[3].y + vo.y;
                float cc = sigmoidf_(gf) * c1 + sigmoidf_(gi) * tanhf_(gg);
                c1 = cc; h1v = sigmoidf_(go) * tanhf_(cc);
            }
            __stcg((float2*)&g_h[dir][buf ^ 1][u][b0], make_float2(h0v, h1v));
            if (s + 1 < S_LEN) {
#pragma unroll
                for (int g = 0; g < 4; g++)
                    gxq[g] = __ldcg((const float2*)(gxd + ((size_t)(s + 1) * 1024 + g * 256 + u) * 128 + b0));
            }
            __threadfence();
        }
        named_bar(barid);
        if (wc == 0) {
            const int tgt = s + 2;
            if (l == 0) g_prog[dir][ch][cl][0] = tgt;
            bool ok;
            do {
                int v0 = g_prog[dir][ch][l][0];
                int v1 = g_prog[dir][ch][l + 32][0];
                ok = (v0 >= tgt) && (v1 >= tgt);
            } while (!__all_sync(0xffffffffu, ok));
            __threadfence();
        }
        named_bar(barid);
    }
    if (ks == 0) {
        g_h0[(size_t)b0 * (2 * HDIM) + dir * HDIM + u]       = h0v;
        g_h0[(size_t)(b0 + 1) * (2 * HDIM) + dir * HDIM + u] = h1v;
    }
}

// ---------------- kernel 4: decoder input gates ------------------------------
__global__ __launch_bounds__(256) void dec_prep_kernel(
    const int* __restrict__ classes, const float* __restrict__ ecW,
    const float* __restrict__ dWih, const float* __restrict__ dbih)
{
    __shared__ float ce[EDIM];
    const int c = blockIdx.x;
    const int cls = classes[c];
    for (int e = threadIdx.x; e < EDIM; e += blockDim.x)
        ce[e] = tanhf_(ecW[(size_t)cls * EDIM + e]);
    __syncthreads();
    const int j = blockIdx.y * 256 + threadIdx.x;
    float acc = dbih[j];
    const float4* w = (const float4*)(dWih + (size_t)j * EDIM);
#pragma unroll 5
    for (int k = 0; k < EDIM / 4; k++) {
        float4 wv = w[k];
        acc += wv.x * ce[4 * k] + wv.y * ce[4 * k + 1] + wv.z * ce[4 * k + 2] + wv.w * ce[4 * k + 3];
    }
    g_gxc[c * 1536 + j] = acc;
}

// ---------------- kernel 5: decoder GRU + proj + cls + log_softmax ----------
__global__ __launch_bounds__(512) void dec_kernel(
    const float* __restrict__ dbhh,
    const float* __restrict__ projW, const float* __restrict__ projB,
    const float* __restrict__ clsW, const float* __restrict__ clsB,
    float* __restrict__ out)
{
    const int Gd = 2;
    const int H2 = 2 * HDIM;
    const int b0 = blockIdx.x * Gd;
    const int u  = threadIdx.x;
    const ulonglong2* W2 = (const ulonglong2*)&g_dWt4[0][0][0];

    __shared__ unsigned long long hd[2][Gd][512];
    __shared__ float hplain[Gd][512];
    __shared__ float projs[Gd][PDIM];
    __shared__ float lgs[Gd][2];

    float hprev[Gd];
#pragma unroll
    for (int b = 0; b < Gd; b++) {
        hprev[b] = g_h0[(size_t)(b0 + b) * H2 + u];
        hd[0][b][u] = pk2(hprev[b], hprev[b]);
    }
    const float bhr = dbhh[u], bhz = dbhh[H2 + u], bhn = dbhh[2 * H2 + u];
    __syncthreads();

    for (int c = 0; c < NCLS; c++) {
        const int cur = c & 1, nxt = cur ^ 1;
        unsigned long long arz[Gd], anp[Gd];
#pragma unroll
        for (int b = 0; b < Gd; b++) { arz[b] = 0ULL; anp[b] = 0ULL; }
        const unsigned long long* h0p = &hd[cur][0][0];
        const unsigned long long* h1p = &hd[cur][1][0];

#pragma unroll 4
        for (int k = 0; k < H2; k++) {
            ulonglong2 wv = W2[k * H2 + u];
            unsigned long long hh0 = h0p[k], hh1 = h1p[k];
            fma2(arz[0], wv.x, hh0); fma2(anp[0], wv.y, hh0);
            fma2(arz[1], wv.x, hh1); fma2(anp[1], wv.y, hh1);
        }
        const float gxr = g_gxc[c * 1536 + u];
        const float gxz = g_gxc[c * 1536 + H2 + u];
        const float gxn = g_gxc[c * 1536 + 2 * H2 + u];
#pragma unroll
        for (int b = 0; b < Gd; b++) {
            float2 vrz = upk2(arz[b]);
            float2 vnp = upk2(anp[b]);
            float r = sigmoidf_(gxr + vrz.x + bhr);
            float z = sigmoidf_(gxz + vrz.y + bhz);
            float n = tanhf_(gxn + r * (vnp.x + bhn));
            float hn = tanhf_((1.0f - z) * n + z * hprev[b]);
            hprev[b] = hn;
            hd[nxt][b][u] = pk2(hn, hn);
            hplain[b][u] = hn;
        }
        __syncthreads();
        {
            const int b = u >> 8, p = u & 255;
            const float4* wv = (const float4*)(projW + (size_t)p * H2);
            const float4* hv = (const float4*)hplain[b];
            float acc = projB[p];
            for (int k4 = 0; k4 < H2 / 4; k4++) {
                float4 w4 = wv[k4], h4 = hv[k4];
                acc += w4.x * h4.x + w4.y * h4.y + w4.z * h4.z + w4.w * h4.w;
            }
            projs[b][p] = acc;
        }
        __syncthreads();
        const int wid = u >> 5, lid = u & 31;
        if (wid < Gd * 2) {
            const int b = wid >> 1, cl = wid & 1;
            float acc = 0.0f;
            for (int k = lid; k < PDIM; k += 32) acc += clsW[cl * PDIM + k] * projs[b][k];
#pragma unroll
            for (int o = 16; o > 0; o >>= 1) acc += __shfl_down_sync(0xffffffffu, acc, o);
            if (lid == 0) lgs[b][cl] = acc + clsB[cl];
        }
        __syncthreads();
        if (u < Gd) {
            const int b = u;
            float l0 = lgs[b][0], l1 = lgs[b][1];
            float m = fmaxf(l0, l1);
            float lse = m + logf(expf(l0 - m) + expf(l1 - m));
            out[(size_t)c * BSZ * 2 + (b0 + b) * 2 + 0] = l0 - lse;
            out[(size_t)c * BSZ * 2 + (b0 + b) * 2 + 1] = l1 - lse;
        }
        __syncthreads();
    }
}

// ---------------- launch -----------------------------------------------------
extern "C" void kernel_launch(void* const* d_in, const int* in_sizes, int n_in,
                              void* d_out, int out_size)
{
    const int*   seq     = (const int*)d_in[0];
    const int*   classes = (const int*)d_in[1];
    const float* embW    = (const float*)d_in[2];
    const float* ecW     = (const float*)d_in[3];
    const float* fWih    = (const float*)d_in[4];
    const float* fWhh    = (const float*)d_in[5];
    const float* fbih    = (const float*)d_in[6];
    const float* fbhh    = (const float*)d_in[7];
    const float* bWih    = (const float*)d_in[8];
    const float* bWhh    = (const float*)d_in[9];
    const float* bbih    = (const float*)d_in[10];
    const float* bbhh    = (const float*)d_in[11];
    const float* dWih    = (const float*)d_in[12];
    const float* dWhh    = (const float*)d_in[13];
    const float* dbih    = (const float*)d_in[14];
    const float* dbhh    = (const float*)d_in[15];
    const float* projW   = (const float*)d_in[16];
    const float* projB   = (const float*)d_in[17];
    const float* clsW    = (const float*)d_in[18];
    const float* clsB    = (const float*)d_in[19];
    float* out = (float*)d_out;

    {   // 0. weight transposes + W fragment pack + progress reset
        dim3 gl(HDIM / 32, HDIM / 32, 8);
        transpose_lstm_w<<<gl, 1024>>>(fWhh, bWhh);
        dim3 gd(2 * HDIM / 32, 2 * HDIM / 32, 3);
        transpose_dec_w<<<gd, 1024>>>(dWhh);
        const int total = 2 * 8 * 8 * NKT8 * 32;
        pack_wfrag<<<(total + 255) / 256, 256>>>(fWih, bWih);
    }
    {   // 1. embeddings (tf32-rounded)
        long long total = (long long)S_LEN * BSZ * EDIM;
        int blocks = (int)((total + 255) / 256);
        embed_kernel<<<blocks, 256>>>(seq, embW);
    }
    {   // 2. input-gate GEMMs on tf32 tensor cores (fragment-packed W)
        dim3 grid(S_LEN, 1024 / 128, 2);
        gx_gemm_tc<<<grid, 256>>>(fbih, fbhh, bbih, bbhh);
    }
    {   // 3. persistent bidirectional LSTM, two chains, dataflow sync
        lstm_persist<<<NCTA_LSTM, 512>>>();
    }
    {   // 4. decoder input gates per class
        dim3 grid(NCLS, 6);
        dec_prep_kernel<<<grid, 256>>>(classes, ecW, dWih, dbih);
    }
    {   // 5. decoder GRU + projection + classifier + log_softmax
        dec_kernel<<<BSZ / 2, 512>>>(dbhh, projW, projB, clsW, clsB, out);
    }
    (void)in_sizes; (void)n_in; (void)out_size;
}

// round 15
// speedup vs baseline: 1.6699x; 1.0171x over previous
#include <cuda_runtime.h>
#include <cuda_bf16.h>
#include <math.h>
#include <stdint.h>

#define S_LEN 512
#define BSZ   128
#define EDIM  300
#define HDIM  256
#define NCLS  6
#define PDIM  256
#define NCTA_LSTM 128            // 64 u-slice CTAs per direction
#define NKT8  38                 // number of 8-k tiles (304 padded)

// ---------------- scratch (device globals; no runtime allocation) ----------
__device__ float g_seq_emb[(size_t)S_LEN * BSZ * EDIM];              // tf32-rounded
__device__ float g_gx[2][(size_t)S_LEN * 4 * HDIM * BSZ];            // [dir][s][col][b] 536 MB
__device__ float g_h[2][2][HDIM][BSZ];                               // [dir][buf][u][b]
__device__ float g_h0[(size_t)BSZ * 2 * HDIM];                       // concat [fh, bh]
__device__ float g_gxc[NCLS * 3 * 2 * HDIM];                         // decoder input gates
__device__ float g_Wt4[2][HDIM][HDIM][4];                            // [dir][k][u][gate i,f,g,o]
__device__ float g_dWt4[2 * HDIM][2 * HDIM][4];                      // [k][u][gate r,z,n,pad]
__device__ float g_Wfrag[2][8][8][NKT8][32][4];                      // tf32 A-fragments, 6.2 MB
// per-CTA progress counters: [dir][chain][cta][pad to 128B] — NO shared atomics
__device__ volatile int g_prog[2][2][64][32];

// ---------------- helpers ---------------------------------------------------
__device__ __forceinline__ float sigmoidf_(float x) { return 1.0f / (1.0f + expf(-x)); }
__device__ __forceinline__ float tanhf_(float x) { return 1.0f - 2.0f / (expf(2.0f * x) + 1.0f); }

__device__ __forceinline__ unsigned long long pk2(float lo, float hi) {
    return ((unsigned long long)__float_as_uint(hi) << 32) | (unsigned long long)__float_as_uint(lo);
}
__device__ __forceinline__ float2 upk2(unsigned long long u) {
    float2 f; f.x = __uint_as_float((unsigned)u); f.y = __uint_as_float((unsigned)(u >> 32)); return f;
}
__device__ __forceinline__ void fma2(unsigned long long& d, unsigned long long a, unsigned long long b) {
    asm("fma.rn.f32x2 %0, %1, %2, %0;" : "+l"(d) : "l"(a), "l"(b));
}
__device__ __forceinline__ void add2(unsigned long long& d, unsigned long long a) {
    asm("add.rn.f32x2 %0, %0, %1;" : "+l"(d) : "l"(a));
}
__device__ __forceinline__ void named_bar(int id) {
    asm volatile("bar.sync %0, 256;" :: "r"(id) : "memory");
}
__device__ __forceinline__ uint32_t f2tf32(float x) {
    uint32_t r; asm("cvt.rna.tf32.f32 %0, %1;" : "=r"(r) : "f"(x)); return r;
}
__device__ __forceinline__ void mma_tf32(float c[4], uint32_t a0, uint32_t a1, uint32_t a2, uint32_t a3,
                                         uint32_t b0, uint32_t b1) {
    asm("mma.sync.aligned.m16n8k8.row.col.f32.tf32.tf32.f32 "
        "{%0,%1,%2,%3}, {%4,%5,%6,%7}, {%8,%9}, {%0,%1,%2,%3};"
        : "+f"(c[0]), "+f"(c[1]), "+f"(c[2]), "+f"(c[3])
        : "r"(a0), "r"(a1), "r"(a2), "r"(a3), "r"(b0), "r"(b1));
}

// ---------------- kernel 0a: transpose LSTM Whh + reset progress ------------
__global__ __launch_bounds__(1024) void transpose_lstm_w(const float* __restrict__ fWhh,
                                                         const float* __restrict__ bWhh)
{
    if (blockIdx.x == 0 && blockIdx.y == 0 && blockIdx.z == 0) {
        for (int i = threadIdx.x; i < 2 * 2 * 64 * 32; i += 1024) ((int*)g_prog)[i] = 0;
    }
    __shared__ float t[32][33];
    const int dir = blockIdx.z >> 2;
    const int g   = blockIdx.z & 3;
    const int k0  = blockIdx.x * 32;
    const int u0  = blockIdx.y * 32;
    const int tx = threadIdx.x & 31, ty = threadIdx.x >> 5;
    const float* W = dir ? bWhh : fWhh;
    t[ty][tx] = W[(size_t)(g * HDIM + u0 + ty) * HDIM + k0 + tx];
    __syncthreads();
    g_Wt4[dir][k0 + ty][u0 + tx][g] = t[tx][ty];
}

// ---------------- kernel 0b: transpose decoder Whh ---------------------------
__global__ __launch_bounds__(1024) void transpose_dec_w(const float* __restrict__ dWhh)
{
    __shared__ float t[32][33];
    const int g  = blockIdx.z;
    const int k0 = blockIdx.x * 32;
    const int u0 = blockIdx.y * 32;
    const int tx = threadIdx.x & 31, ty = threadIdx.x >> 5;
    t[ty][tx] = dWhh[(size_t)(g * 2 * HDIM + u0 + ty) * (2 * HDIM) + k0 + tx];
    __syncthreads();
    g_dWt4[k0 + ty][u0 + tx][g] = t[tx][ty];
}

// ---------------- kernel 0c: pack Wih into tf32 mma A-fragments --------------
__global__ __launch_bounds__(256) void pack_wfrag(const float* __restrict__ fWih,
                                                  const float* __restrict__ bWih)
{
    const int idx = blockIdx.x * 256 + threadIdx.x;
    const int total = 2 * 8 * 8 * NKT8 * 32;
    if (idx >= total) return;
    const int lane  = idx & 31;
    const int kt    = (idx >> 5) % NKT8;
    const int warp  = ((idx >> 5) / NKT8) & 7;
    const int ntile = ((idx >> 5) / (NKT8 * 8)) & 7;
    const int dir   = idx / (32 * NKT8 * 8 * 8);
    const float* W = dir ? bWih : fWih;
    const int grp = lane >> 2, tig = lane & 3;
    const int col0 = ntile * 128 + warp * 16 + grp;
    const int col1 = col0 + 8;
    const int k0 = kt * 8 + tig, k1 = k0 + 4;
    float a0 = (k0 < EDIM) ? W[(size_t)col0 * EDIM + k0] : 0.f;
    float a1 = (k0 < EDIM) ? W[(size_t)col1 * EDIM + k0] : 0.f;
    float a2 = (k1 < EDIM) ? W[(size_t)col0 * EDIM + k1] : 0.f;
    float a3 = (k1 < EDIM) ? W[(size_t)col1 * EDIM + k1] : 0.f;
    float* dst = &g_Wfrag[dir][ntile][warp][kt][lane][0];
    dst[0] = __uint_as_float(f2tf32(a0));
    dst[1] = __uint_as_float(f2tf32(a1));
    dst[2] = __uint_as_float(f2tf32(a2));
    dst[3] = __uint_as_float(f2tf32(a3));
}

// ---------------- kernel 1: embedding gather + tanh + tf32 round ------------
__global__ void embed_kernel(const int* __restrict__ seq, const float* __restrict__ embW) {
    long long idx = (long long)blockIdx.x * blockDim.x + threadIdx.x;
    const long long total = (long long)S_LEN * BSZ * EDIM;
    if (idx >= total) return;
    int e = (int)(idx % EDIM);
    int r = (int)(idx / EDIM);
    int b = r % BSZ;
    int s = r / BSZ;
    int v = seq[b * S_LEN + s];
    g_seq_emb[idx] = __uint_as_float(f2tf32(tanhf_(embW[(long long)v * EDIM + e])));
}

// ---------------- kernel 2: input GEMMs via tf32 tensor cores (v3) ----------
// GRID REORDER for L2 reuse: blockIdx.x = ntile + 8*dir (16), blockIdx.y = s.
// The 16 CTAs sharing an emb slab are now wave-adjacent -> slab read once
// from DRAM, reused 8x from L2 (emb DRAM traffic 1.26GB -> ~160MB).
__global__ __launch_bounds__(256) void gx_gemm_tc(
    const float* __restrict__ fbih, const float* __restrict__ fbhh,
    const float* __restrict__ bbih, const float* __restrict__ bbhh)
{
    __shared__ uint32_t Es[2][16][136];

    const int ntile = blockIdx.x & 7;
    const int dir   = blockIdx.x >> 3;
    const int s     = blockIdx.y;
    const float* bi = dir ? bbih : fbih;
    const float* bh = dir ? bbhh : fbhh;
    const int src_s = dir ? ((S_LEN - s) & (S_LEN - 1)) : s;
    const float* Abase = g_seq_emb + (size_t)src_s * BSZ * EDIM;

    const int t    = threadIdx.x;
    const int lane = t & 31;
    const int warp = t >> 5;
    const int grp  = lane >> 2;          // 0..7
    const int tig  = lane & 3;           // 0..3

    const int colg0 = ntile * 128 + warp * 16 + grp;
    const int colg1 = colg0 + 8;
    const float bias0 = bi[colg0] + bh[colg0];
    const float bias1 = bi[colg1] + bh[colg1];
    float c[16][4];
#pragma unroll
    for (int nt = 0; nt < 16; nt++) {
        c[nt][0] = bias0; c[nt][1] = bias0;
        c[nt][2] = bias1; c[nt][3] = bias1;
    }

    // W fragment stream (fragment-major, stride 32 float4 per 8-k tile)
    const float4* wf = (const float4*)&g_Wfrag[dir][ntile][warp][0][lane][0];
    float4 af0 = wf[0];
    float4 af1 = wf[32];

    // E staging map: thread -> (row = t>>1, k-half = (t&1)*8)
    const int srow = t >> 1;
    const int kh   = (t & 1) * 8;
    const int NK2  = (NKT8 + 1) / 2;     // 19 BK=16 iterations

    float4 evA = make_float4(0.f, 0.f, 0.f, 0.f);
    float4 evB = make_float4(0.f, 0.f, 0.f, 0.f);
    {
        const int kk = kh;
        if (kk + 3 < EDIM)  evA = *(const float4*)(Abase + (size_t)srow * EDIM + kk);
        if (kk + 7 < EDIM)  evB = *(const float4*)(Abase + (size_t)srow * EDIM + kk + 4);
    }
    Es[0][kh + 0][srow] = __float_as_uint(evA.x); Es[0][kh + 1][srow] = __float_as_uint(evA.y);
    Es[0][kh + 2][srow] = __float_as_uint(evA.z); Es[0][kh + 3][srow] = __float_as_uint(evA.w);
    Es[0][kh + 4][srow] = __float_as_uint(evB.x); Es[0][kh + 5][srow] = __float_as_uint(evB.y);
    Es[0][kh + 6][srow] = __float_as_uint(evB.z); Es[0][kh + 7][srow] = __float_as_uint(evB.w);

    for (int kt2 = 0; kt2 < NK2; kt2++) {
        __syncthreads();
        const int cur = kt2 & 1;
        const bool more = (kt2 + 1 < NK2);
        if (more) {
            const int kk = (kt2 + 1) * 16 + kh;
            evA = make_float4(0.f, 0.f, 0.f, 0.f);
            evB = make_float4(0.f, 0.f, 0.f, 0.f);
            if (kk + 3 < EDIM) evA = *(const float4*)(Abase + (size_t)srow * EDIM + kk);
            if (kk + 7 < EDIM) evB = *(const float4*)(Abase + (size_t)srow * EDIM + kk + 4);
        }
        // half-tile 0 (k = kt2*16 .. +7)
        {
            uint32_t a0 = __float_as_uint(af0.x), a1 = __float_as_uint(af0.y);
            uint32_t a2 = __float_as_uint(af0.z), a3 = __float_as_uint(af0.w);
#pragma unroll
            for (int nt = 0; nt < 16; nt++) {
                uint32_t b0 = Es[cur][tig][nt * 8 + grp];
                uint32_t b1 = Es[cur][tig + 4][nt * 8 + grp];
                mma_tf32(c[nt], a0, a1, a2, a3, b0, b1);
            }
        }
        // half-tile 1 (k = kt2*16+8 .. +15)
        {
            uint32_t a0 = __float_as_uint(af1.x), a1 = __float_as_uint(af1.y);
            uint32_t a2 = __float_as_uint(af1.z), a3 = __float_as_uint(af1.w);
#pragma unroll
            for (int nt = 0; nt < 16; nt++) {
                uint32_t b0 = Es[cur][8 + tig][nt * 8 + grp];
                uint32_t b1 = Es[cur][8 + tig + 4][nt * 8 + grp];
                mma_tf32(c[nt], a0, a1, a2, a3, b0, b1);
            }
        }
        if (more) {
            af0 = wf[(2 * kt2 + 2) * 32];
            af1 = wf[(2 * kt2 + 3) * 32];
            const int nxt = cur ^ 1;
            Es[nxt][kh + 0][srow] = __float_as_uint(evA.x); Es[nxt][kh + 1][srow] = __float_as_uint(evA.y);
            Es[nxt][kh + 2][srow] = __float_as_uint(evA.z); Es[nxt][kh + 3][srow] = __float_as_uint(evA.w);
            Es[nxt][kh + 4][srow] = __float_as_uint(evB.x); Es[nxt][kh + 5][srow] = __float_as_uint(evB.y);
            Es[nxt][kh + 6][srow] = __float_as_uint(evB.z); Es[nxt][kh + 7][srow] = __float_as_uint(evB.w);
        }
    }
    // epilogue: D(row=col, col=batch) -> g_gx[dir][s][col][b], float2 stores
    float* gbase = g_gx[dir] + (size_t)s * 1024 * 128;
#pragma unroll
    for (int nt = 0; nt < 16; nt++) {
        const int b = nt * 8 + 2 * tig;
        *(float2*)(gbase + (size_t)colg0 * 128 + b) = make_float2(c[nt][0], c[nt][1]);
        *(float2*)(gbase + (size_t)colg1 * 128 + b) = make_float2(c[nt][2], c[nt][3]);
    }
}

// ---------------- kernel 3: persistent LSTM, two chains, dataflow sync ------
// (unchanged — current best)
__global__ __launch_bounds__(512) void lstm_persist()
{
    __shared__ unsigned long long wd[HDIM][4][4];     // dup'd weight pairs, 32KB
    __shared__ unsigned long long part[2][4][32][4];  // [chain][wb][lane][g] partials, 8KB

    const int cta = blockIdx.x;
    const int dir = cta >> 6;
    const int cl  = cta & 63;
    const int u0  = cl * 4;
    const int t   = threadIdx.x;
    const int w   = t >> 5;
    const int l   = t & 31;
    const int ch  = w >> 3;
    const int wc  = w & 7;
    const int ks  = wc >> 2;
    const int wb  = wc & 3;
    const int ul  = l >> 3;
    const int bp  = l & 7;
    const int u   = u0 + ul;
    const int b0  = ch * 64 + wb * 16 + 2 * bp;
    const int kbase = ks * 128;
    const int barid = ch + 1;

    for (int e = t; e < 256 * 16; e += 512) {
        int k = e >> 4, ui = (e >> 2) & 3, g = e & 3;
        float wv = g_Wt4[dir][k][u0 + ui][g];
        wd[k][ui][g] = pk2(wv, wv);
    }
    float c0 = 0.f, c1 = 0.f, h0v = 0.f, h1v = 0.f;
    if (ks == 0) {
        *(float2*)&g_h[dir][0][u][b0] = make_float2(0.f, 0.f);
        __threadfence();
    }
    __syncthreads();

    if (wc == 0) {
        if (l == 0) g_prog[dir][ch][cl][0] = 1;
        bool ok;
        do {
            int v0 = g_prog[dir][ch][l][0];
            int v1 = g_prog[dir][ch][l + 32][0];
            ok = (v0 >= 1) && (v1 >= 1);
        } while (!__all_sync(0xffffffffu, ok));
        __threadfence();
    }
    named_bar(barid);

    const float* gxd = g_gx[dir];
    float2 gxq[4];
    if (ks == 0) {
#pragma unroll
        for (int g = 0; g < 4; g++)
            gxq[g] = __ldcg((const float2*)(gxd + ((size_t)0 * 1024 + g * 256 + u) * 128 + b0));
    }

    for (int s = 0; s < S_LEN; s++) {
        const int buf = s & 1;
        const float* hb = &g_h[dir][buf][0][0] + kbase * 128 + b0;

        unsigned long long acc[4] = {0ULL, 0ULL, 0ULL, 0ULL};
        unsigned long long hpA[8], hpB[8];
#pragma unroll
        for (int i = 0; i < 8; i++) hpA[i] = __ldcg((const unsigned long long*)(hb + i * 128));
#pragma unroll
        for (int i = 0; i < 8; i++) hpB[i] = __ldcg((const unsigned long long*)(hb + (8 + i) * 128));

        for (int kc = 0; kc < 16; kc += 2) {
            const int kA = kbase + kc * 8, kB = kA + 8;
#pragma unroll
            for (int i = 0; i < 8; i++) {
                ulonglong2 wif = *(const ulonglong2*)&wd[kA + i][ul][0];
                ulonglong2 wgo = *(const ulonglong2*)&wd[kA + i][ul][2];
                fma2(acc[0], wif.x, hpA[i]); fma2(acc[1], wif.y, hpA[i]);
                fma2(acc[2], wgo.x, hpA[i]); fma2(acc[3], wgo.y, hpA[i]);
            }
            if (kc + 2 < 16) {
                const float* src = hb + (kc + 2) * 8 * 128;
#pragma unroll
                for (int i = 0; i < 8; i++) hpA[i] = __ldcg((const unsigned long long*)(src + i * 128));
            }
#pragma unroll
            for (int i = 0; i < 8; i++) {
                ulonglong2 wif = *(const ulonglong2*)&wd[kB + i][ul][0];
                ulonglong2 wgo = *(const ulonglong2*)&wd[kB + i][ul][2];
                fma2(acc[0], wif.x, hpB[i]); fma2(acc[1], wif.y, hpB[i]);
                fma2(acc[2], wgo.x, hpB[i]); fma2(acc[3], wgo.y, hpB[i]);
            }
            if (kc + 3 < 16) {
                const float* src = hb + (kc + 3) * 8 * 128;
#pragma unroll
                for (int i = 0; i < 8; i++) hpB[i] = __ldcg((const unsigned long long*)(src + i * 128));
            }
        }
        if (ks == 1) {
            *(ulonglong2*)&part[ch][wb][l][0] = make_ulonglong2(acc[0], acc[1]);
            *(ulonglong2*)&part[ch][wb][l][2] = make_ulonglong2(acc[2], acc[3]);
        }
        named_bar(barid);
        if (ks == 0) {
            ulonglong2 p01 = *(const ulonglong2*)&part[ch][wb][l][0];
            ulonglong2 p23 = *(const ulonglong2*)&part[ch][wb][l][2];
            add2(acc[0], p01.x); add2(acc[1], p01.y);
            add2(acc[2], p23.x); add2(acc[3], p23.y);
            float2 vi = upk2(acc[0]), vf = upk2(acc[1]), vg = upk2(acc[2]), vo = upk2(acc[3]);
            {
                float gi = gxq[0].x + vi.x, gf = gxq[1].x + vf.x;
                float gg = gxq[2].x + vg.x, go = gxq[3].x + vo.x;
                float cc = sigmoidf_(gf) * c0 + sigmoidf_(gi) * tanhf_(gg);
                c0 = cc; h0v = sigmoidf_(go) * tanhf_(cc);
            }
            {
                float gi = gxq[0].y + vi.y, gf = gxq[1].y + vf.y;
                float gg = gxq[2].y + vg.y, go = gxq[3].y + vo.y;
                float cc = sigmoidf_(gf) * c1 + sigmoidf_(gi) * tanhf_(gg);
                c1 = cc; h1v = sigmoidf_(go) * tanhf_(cc);
            }
            __stcg((float2*)&g_h[dir][buf ^ 1][u][b0], make_float2(h0v, h1v));
            if (s + 1 < S_LEN) {
#pragma unroll
                for (int g = 0; g < 4; g++)
                    gxq[g] = __ldcg((const float2*)(gxd + ((size_t)(s + 1) * 1024 + g * 256 + u) * 128 + b0));
            }
            __threadfence();
        }
        named_bar(barid);
        if (wc == 0) {
            const int tgt = s + 2;
            if (l == 0) g_prog[dir][ch][cl][0] = tgt;
            bool ok;
            do {
                int v0 = g_prog[dir][ch][l][0];
                int v1 = g_prog[dir][ch][l + 32][0];
                ok = (v0 >= tgt) && (v1 >= tgt);
            } while (!__all_sync(0xffffffffu, ok));
            __threadfence();
        }
        named_bar(barid);
    }
    if (ks == 0) {
        g_h0[(size_t)b0 * (2 * HDIM) + dir * HDIM + u]       = h0v;
        g_h0[(size_t)(b0 + 1) * (2 * HDIM) + dir * HDIM + u] = h1v;
    }
}

// ---------------- kernel 4: decoder input gates ------------------------------
__global__ __launch_bounds__(256) void dec_prep_kernel(
    const int* __restrict__ classes, const float* __restrict__ ecW,
    const float* __restrict__ dWih, const float* __restrict__ dbih)
{
    __shared__ float ce[EDIM];
    const int c = blockIdx.x;
    const int cls = classes[c];
    for (int e = threadIdx.x; e < EDIM; e += blockDim.x)
        ce[e] = tanhf_(ecW[(size_t)cls * EDIM + e]);
    __syncthreads();
    const int j = blockIdx.y * 256 + threadIdx.x;
    float acc = dbih[j];
    const float4* w = (const float4*)(dWih + (size_t)j * EDIM);
#pragma unroll 5
    for (int k = 0; k < EDIM / 4; k++) {
        float4 wv = w[k];
        acc += wv.x * ce[4 * k] + wv.y * ce[4 * k + 1] + wv.z * ce[4 * k + 2] + wv.w * ce[4 * k + 3];
    }
    g_gxc[c * 1536 + j] = acc;
}

// ---------------- kernel 5: decoder GRU + proj + cls + log_softmax ----------
__global__ __launch_bounds__(512) void dec_kernel(
    const float* __restrict__ dbhh,
    const float* __restrict__ projW, const float* __restrict__ projB,
    const float* __restrict__ clsW, const float* __restrict__ clsB,
    float* __restrict__ out)
{
    const int Gd = 2;
    const int H2 = 2 * HDIM;
    const int b0 = blockIdx.x * Gd;
    const int u  = threadIdx.x;
    const ulonglong2* W2 = (const ulonglong2*)&g_dWt4[0][0][0];

    __shared__ unsigned long long hd[2][Gd][512];
    __shared__ float hplain[Gd][512];
    __shared__ float projs[Gd][PDIM];
    __shared__ float lgs[Gd][2];

    float hprev[Gd];
#pragma unroll
    for (int b = 0; b < Gd; b++) {
        hprev[b] = g_h0[(size_t)(b0 + b) * H2 + u];
        hd[0][b][u] = pk2(hprev[b], hprev[b]);
    }
    const float bhr = dbhh[u], bhz = dbhh[H2 + u], bhn = dbhh[2 * H2 + u];
    __syncthreads();

    for (int c = 0; c < NCLS; c++) {
        const int cur = c & 1, nxt = cur ^ 1;
        unsigned long long arz[Gd], anp[Gd];
#pragma unroll
        for (int b = 0; b < Gd; b++) { arz[b] = 0ULL; anp[b] = 0ULL; }
        const unsigned long long* h0p = &hd[cur][0][0];
        const unsigned long long* h1p = &hd[cur][1][0];

#pragma unroll 4
        for (int k = 0; k < H2; k++) {
            ulonglong2 wv = W2[k * H2 + u];
            unsigned long long hh0 = h0p[k], hh1 = h1p[k];
            fma2(arz[0], wv.x, hh0); fma2(anp[0], wv.y, hh0);
            fma2(arz[1], wv.x, hh1); fma2(anp[1], wv.y, hh1);
        }
        const float gxr = g_gxc[c * 1536 + u];
        const float gxz = g_gxc[c * 1536 + H2 + u];
        const float gxn = g_gxc[c * 1536 + 2 * H2 + u];
#pragma unroll
        for (int b = 0; b < Gd; b++) {
            float2 vrz = upk2(arz[b]);
            float2 vnp = upk2(anp[b]);
            float r = sigmoidf_(gxr + vrz.x + bhr);
            float z = sigmoidf_(gxz + vrz.y + bhz);
            float n = tanhf_(gxn + r * (vnp.x + bhn));
            float hn = tanhf_((1.0f - z) * n + z * hprev[b]);
            hprev[b] = hn;
            hd[nxt][b][u] = pk2(hn, hn);
            hplain[b][u] = hn;
        }
        __syncthreads();
        {
            const int b = u >> 8, p = u & 255;
            const float4* wv = (const float4*)(projW + (size_t)p * H2);
            const float4* hv = (const float4*)hplain[b];
            float acc = projB[p];
            for (int k4 = 0; k4 < H2 / 4; k4++) {
                float4 w4 = wv[k4], h4 = hv[k4];
                acc += w4.x * h4.x + w4.y * h4.y + w4.z * h4.z + w4.w * h4.w;
            }
            projs[b][p] = acc;
        }
        __syncthreads();
        const int wid = u >> 5, lid = u & 31;
        if (wid < Gd * 2) {
            const int b = wid >> 1, cl = wid & 1;
            float acc = 0.0f;
            for (int k = lid; k < PDIM; k += 32) acc += clsW[cl * PDIM + k] * projs[b][k];
#pragma unroll
            for (int o = 16; o > 0; o >>= 1) acc += __shfl_down_sync(0xffffffffu, acc, o);
            if (lid == 0) lgs[b][cl] = acc + clsB[cl];
        }
        __syncthreads();
        if (u < Gd) {
            const int b = u;
            float l0 = lgs[b][0], l1 = lgs[b][1];
            float m = fmaxf(l0, l1);
            float lse = m + logf(expf(l0 - m) + expf(l1 - m));
            out[(size_t)c * BSZ * 2 + (b0 + b) * 2 + 0] = l0 - lse;
            out[(size_t)c * BSZ * 2 + (b0 + b) * 2 + 1] = l1 - lse;
        }
        __syncthreads();
    }
}

// ---------------- launch -----------------------------------------------------
extern "C" void kernel_launch(void* const* d_in, const int* in_sizes, int n_in,
                              void* d_out, int out_size)
{
    const int*   seq     = (const int*)d_in[0];
    const int*   classes = (const int*)d_in[1];
    const float* embW    = (const float*)d_in[2];
    const float* ecW     = (const float*)d_in[3];
    const float* fWih    = (const float*)d_in[4];
    const float* fWhh    = (const float*)d_in[5];
    const float* fbih    = (const float*)d_in[6];
    const float* fbhh    = (const float*)d_in[7];
    const float* bWih    = (const float*)d_in[8];
    const float* bWhh    = (const float*)d_in[9];
    const float* bbih    = (const float*)d_in[10];
    const float* bbhh    = (const float*)d_in[11];
    const float* dWih    = (const float*)d_in[12];
    const float* dWhh    = (const float*)d_in[13];
    const float* dbih    = (const float*)d_in[14];
    const float* dbhh    = (const float*)d_in[15];
    const float* projW   = (const float*)d_in[16];
    const float* projB   = (const float*)d_in[17];
    const float* clsW    = (const float*)d_in[18];
    const float* clsB    = (const float*)d_in[19];
    float* out = (float*)d_out;

    {   // 0. weight transposes + W fragment pack + progress reset
        dim3 gl(HDIM / 32, HDIM / 32, 8);
        transpose_lstm_w<<<gl, 1024>>>(fWhh, bWhh);
        dim3 gd(2 * HDIM / 32, 2 * HDIM / 32, 3);
        transpose_dec_w<<<gd, 1024>>>(dWhh);
        const int total = 2 * 8 * 8 * NKT8 * 32;
        pack_wfrag<<<(total + 255) / 256, 256>>>(fWih, bWih);
    }
    {   // 1. embeddings (tf32-rounded)
        long long total = (long long)S_LEN * BSZ * EDIM;
        int blocks = (int)((total + 255) / 256);
        embed_kernel<<<blocks, 256>>>(seq, embW);
    }
    {   // 2. input-gate GEMMs on tf32 tensor cores — L2-reuse grid order
        dim3 grid(16, S_LEN);
        gx_gemm_tc<<<grid, 256>>>(fbih, fbhh, bbih, bbhh);
    }
    {   // 3. persistent bidirectional LSTM, two chains, dataflow sync
        lstm_persist<<<NCTA_LSTM, 512>>>();
    }
    {   // 4. decoder input gates per class
        dim3 grid(NCLS, 6);
        dec_prep_kernel<<<grid, 256>>>(classes, ecW, dWih, dbih);
    }
    {   // 5. decoder GRU + projection + classifier + log_softmax
        dec_kernel<<<BSZ / 2, 512>>>(dbhh, projW, projB, clsW, clsB, out);
    }
    (void)in_sizes; (void)n_in; (void)out_size;
}